// round 1
// baseline (speedup 1.0000x reference)
#include <cuda_runtime.h>
#include <cstdint>

#define NS 4
#define CD 2048
#define FLT 8192
#define BR 4096
#define DFF 8192

// Scratch (static device arrays: allowed, no runtime allocation)
__device__ float g_fin[(size_t)BR * CD];        // (B, C)   32 MB
__device__ float g_hidden[(size_t)BR * DFF];    // (B, DFF) 128 MB
__device__ float g_hpost[BR * NS];              // (B, 4)

// ---------------------------------------------------------------- helpers
__device__ __forceinline__ float fast_tanhf(float u) {
    // tanh(u) = 1 - 2/(exp(2u)+1); stable at both ends, ~1e-6 error
    float e = __expf(2.0f * u);
    return 1.0f - __fdividef(2.0f, e + 1.0f);
}

__device__ __forceinline__ float gelu_tanh(float x) {
    // matches jax.nn.gelu (approximate=True)
    float u = 0.7978845608028654f * fmaf(0.044715f * x, x * x, x);
    return 0.5f * x * (1.0f + fast_tanhf(u));
}

__device__ __forceinline__ uint32_t f2tf32(float x) {
    uint32_t u;
    asm("cvt.rna.tf32.f32 %0, %1;" : "=r"(u) : "f"(x));
    return u;
}

// ---------------------------------------------------------------- gates
// One block per batch row b. Computes rms-norm dot products against
// phi_pre/phi_post/phi_res (24 dots + sumsq), sigmoid / 2*sigmoid gates,
// 20-iteration Sinkhorn on the 4x4 H_res, then writes:
//   g_fin[b, :]   = sum_n Hpre[n] * x[b, n, :]
//   out[b, m, :]  = sum_n Hres[m][n] * x[b, n, :]   (residuals)
//   g_hpost[b, :] = 2*sigmoid(H_post_t)
__global__ __launch_bounds__(256) void gates_kernel(
    const float* __restrict__ x,
    const float* __restrict__ phi_pre,
    const float* __restrict__ phi_post,
    const float* __restrict__ phi_res,
    const float* __restrict__ bias_pre,
    const float* __restrict__ bias_post,
    const float* __restrict__ bias_res,
    const float* __restrict__ alpha_pre_p,
    const float* __restrict__ alpha_post_p,
    const float* __restrict__ alpha_res_p,
    float* __restrict__ out)
{
    __shared__ float sx[FLT];
    __shared__ float sred[8][25];
    __shared__ float sdot[25];
    __shared__ float sg[20];   // [0..3] Hpre, [4..19] Hres (row-major)

    const int tid = threadIdx.x;
    const int b = blockIdx.x;

    const float4* xr = (const float4*)(x + (size_t)b * FLT);
    float4* sx4 = (float4*)sx;
    #pragma unroll 4
    for (int i = tid; i < FLT / 4; i += 256) sx4[i] = xr[i];
    __syncthreads();

    float acc[25];
    #pragma unroll
    for (int j = 0; j < 25; j++) acc[j] = 0.0f;

    const float4* pp4 = (const float4*)phi_pre;
    const float4* pq4 = (const float4*)phi_post;
    const float4* pr4 = (const float4*)phi_res;

    for (int f = tid; f < FLT; f += 256) {
        float xv = sx[f];
        acc[24] = fmaf(xv, xv, acc[24]);
        float4 p = pp4[f];
        acc[0] = fmaf(xv, p.x, acc[0]);
        acc[1] = fmaf(xv, p.y, acc[1]);
        acc[2] = fmaf(xv, p.z, acc[2]);
        acc[3] = fmaf(xv, p.w, acc[3]);
        float4 q = pq4[f];
        acc[4] = fmaf(xv, q.x, acc[4]);
        acc[5] = fmaf(xv, q.y, acc[5]);
        acc[6] = fmaf(xv, q.z, acc[6]);
        acc[7] = fmaf(xv, q.w, acc[7]);
        #pragma unroll
        for (int r = 0; r < 4; r++) {
            float4 rr = pr4[f * 4 + r];
            acc[8 + r*4 + 0] = fmaf(xv, rr.x, acc[8 + r*4 + 0]);
            acc[8 + r*4 + 1] = fmaf(xv, rr.y, acc[8 + r*4 + 1]);
            acc[8 + r*4 + 2] = fmaf(xv, rr.z, acc[8 + r*4 + 2]);
            acc[8 + r*4 + 3] = fmaf(xv, rr.w, acc[8 + r*4 + 3]);
        }
    }

    const int lane = tid & 31, warp = tid >> 5;
    #pragma unroll
    for (int j = 0; j < 25; j++) {
        float v = acc[j];
        v += __shfl_xor_sync(0xffffffffu, v, 16);
        v += __shfl_xor_sync(0xffffffffu, v, 8);
        v += __shfl_xor_sync(0xffffffffu, v, 4);
        v += __shfl_xor_sync(0xffffffffu, v, 2);
        v += __shfl_xor_sync(0xffffffffu, v, 1);
        if (lane == 0) sred[warp][j] = v;
    }
    __syncthreads();
    if (tid < 25) {
        float s = 0.0f;
        #pragma unroll
        for (int w = 0; w < 8; w++) s += sred[w][tid];
        sdot[tid] = s;
    }
    __syncthreads();
    if (tid == 0) {
        float inv_rms = rsqrtf(sdot[24] * (1.0f / (float)FLT) + 1e-8f);
        float a_pre = alpha_pre_p[0], a_post = alpha_post_p[0], a_res = alpha_res_p[0];
        #pragma unroll
        for (int n = 0; n < 4; n++) {
            float tpre = fmaf(a_pre, sdot[n] * inv_rms, bias_pre[n]);
            sg[n] = 1.0f / (1.0f + expf(-tpre));
            float tpost = fmaf(a_post, sdot[4 + n] * inv_rms, bias_post[n]);
            g_hpost[b * 4 + n] = 2.0f / (1.0f + expf(-tpost));
        }
        float M[4][4];
        #pragma unroll
        for (int m = 0; m < 4; m++)
            #pragma unroll
            for (int n = 0; n < 4; n++)
                M[m][n] = expf(fmaf(a_res, sdot[8 + m*4 + n] * inv_rms, bias_res[m*4 + n]));
        #pragma unroll 1
        for (int it = 0; it < 20; it++) {
            #pragma unroll
            for (int m = 0; m < 4; m++) {
                float rs = M[m][0] + M[m][1] + M[m][2] + M[m][3] + 1e-12f;
                float inv = 1.0f / rs;
                M[m][0] *= inv; M[m][1] *= inv; M[m][2] *= inv; M[m][3] *= inv;
            }
            #pragma unroll
            for (int n = 0; n < 4; n++) {
                float cs = M[0][n] + M[1][n] + M[2][n] + M[3][n] + 1e-12f;
                float inv = 1.0f / cs;
                M[0][n] *= inv; M[1][n] *= inv; M[2][n] *= inv; M[3][n] *= inv;
            }
        }
        #pragma unroll
        for (int m = 0; m < 4; m++)
            #pragma unroll
            for (int n = 0; n < 4; n++)
                sg[4 + m*4 + n] = M[m][n];
    }
    __syncthreads();

    const float h0 = sg[0], h1 = sg[1], h2 = sg[2], h3 = sg[3];
    float R[4][4];
    #pragma unroll
    for (int m = 0; m < 4; m++)
        #pragma unroll
        for (int n = 0; n < 4; n++)
            R[m][n] = sg[4 + m*4 + n];

    float4* fin4 = (float4*)(g_fin + (size_t)b * CD);
    #pragma unroll 1
    for (int c = tid; c < CD / 4; c += 256) {
        float4 x0 = sx4[c];
        float4 x1 = sx4[512 + c];
        float4 x2 = sx4[1024 + c];
        float4 x3 = sx4[1536 + c];
        float4 fv;
        fv.x = h0*x0.x + h1*x1.x + h2*x2.x + h3*x3.x;
        fv.y = h0*x0.y + h1*x1.y + h2*x2.y + h3*x3.y;
        fv.z = h0*x0.z + h1*x1.z + h2*x2.z + h3*x3.z;
        fv.w = h0*x0.w + h1*x1.w + h2*x2.w + h3*x3.w;
        fin4[c] = fv;
        #pragma unroll
        for (int m = 0; m < 4; m++) {
            float4 ov;
            ov.x = R[m][0]*x0.x + R[m][1]*x1.x + R[m][2]*x2.x + R[m][3]*x3.x;
            ov.y = R[m][0]*x0.y + R[m][1]*x1.y + R[m][2]*x2.y + R[m][3]*x3.y;
            ov.z = R[m][0]*x0.z + R[m][1]*x1.z + R[m][2]*x2.z + R[m][3]*x3.z;
            ov.w = R[m][0]*x0.w + R[m][1]*x1.w + R[m][2]*x2.w + R[m][3]*x3.w;
            ((float4*)(out + ((size_t)b * 4 + m) * CD))[c] = ov;
        }
    }
}

// ---------------------------------------------------------------- tf32 GEMM
// Block tile 128x128, BK=32, 256 threads (8 warps as 2x4), warp tile 64x32,
// mma.sync.m16n8k8.tf32 with fp32 accumulate. Padded shared layouts give
// conflict-free fragment reads (PA%32==4, PB%32==8).
#define PA 36
#define PB 136

__device__ __forceinline__ void gemm_mainloop(
    const float* __restrict__ A, const float* __restrict__ Bm,
    const int KDIM, const int NDIM, const int bm0, const int bn0,
    uint32_t* __restrict__ As, uint32_t* __restrict__ Bs,
    float acc[4][4][4])
{
    const int tid = threadIdx.x;
    const int lane = tid & 31;
    const int warp = tid >> 5;
    const int wm = warp >> 2;     // 0..1
    const int wn = warp & 3;      // 0..3
    const int gid = lane >> 2;    // 0..7
    const int tig = lane & 3;     // 0..3

    for (int kt = 0; kt < KDIM; kt += 32) {
        // A tile: 128 x 32, row-major source
        #pragma unroll
        for (int i = 0; i < 4; i++) {
            int idx = i * 256 + tid;
            int ar = idx >> 3;
            int ac = (idx & 7) << 2;
            float4 v = *(const float4*)(A + (size_t)(bm0 + ar) * KDIM + kt + ac);
            uint4 u = make_uint4(f2tf32(v.x), f2tf32(v.y), f2tf32(v.z), f2tf32(v.w));
            *(uint4*)(As + ar * PA + ac) = u;
        }
        // B tile: 32 x 128, row-major source
        #pragma unroll
        for (int i = 0; i < 4; i++) {
            int idx = i * 256 + tid;
            int br = idx >> 5;
            int bc = (idx & 31) << 2;
            float4 v = *(const float4*)(Bm + (size_t)(kt + br) * NDIM + bn0 + bc);
            uint4 u = make_uint4(f2tf32(v.x), f2tf32(v.y), f2tf32(v.z), f2tf32(v.w));
            *(uint4*)(Bs + br * PB + bc) = u;
        }
        __syncthreads();
        #pragma unroll
        for (int kk = 0; kk < 4; kk++) {
            const int k0 = kk * 8;
            uint32_t af[4][4];
            #pragma unroll
            for (int mi = 0; mi < 4; mi++) {
                const uint32_t* ap = As + (wm*64 + mi*16 + gid) * PA + k0 + tig;
                af[mi][0] = ap[0];           // (row gid,   k tig)
                af[mi][1] = ap[8 * PA];      // (row gid+8, k tig)
                af[mi][2] = ap[4];           // (row gid,   k tig+4)
                af[mi][3] = ap[8 * PA + 4];  // (row gid+8, k tig+4)
            }
            uint32_t bf[4][2];
            #pragma unroll
            for (int ni = 0; ni < 4; ni++) {
                const uint32_t* bp = Bs + (k0 + tig) * PB + wn*32 + ni*8 + gid;
                bf[ni][0] = bp[0];           // (k tig,   n gid)
                bf[ni][1] = bp[4 * PB];      // (k tig+4, n gid)
            }
            #pragma unroll
            for (int mi = 0; mi < 4; mi++)
                #pragma unroll
                for (int ni = 0; ni < 4; ni++)
                    asm volatile(
                        "mma.sync.aligned.m16n8k8.row.col.f32.tf32.tf32.f32 "
                        "{%0,%1,%2,%3}, {%4,%5,%6,%7}, {%8,%9}, {%0,%1,%2,%3};\n"
                        : "+f"(acc[mi][ni][0]), "+f"(acc[mi][ni][1]),
                          "+f"(acc[mi][ni][2]), "+f"(acc[mi][ni][3])
                        : "r"(af[mi][0]), "r"(af[mi][1]), "r"(af[mi][2]), "r"(af[mi][3]),
                          "r"(bf[ni][0]), "r"(bf[ni][1]));
        }
        __syncthreads();
    }
}

// GEMM1: hidden = gelu(fin @ W1 + b1)   M=4096, N=8192, K=2048
__global__ __launch_bounds__(256) void gemm1_kernel(
    const float* __restrict__ W1, const float* __restrict__ b1)
{
    __shared__ __align__(16) uint32_t As[128 * PA];
    __shared__ __align__(16) uint32_t Bs[32 * PB];
    float acc[4][4][4];
    #pragma unroll
    for (int i = 0; i < 4; i++)
        #pragma unroll
        for (int j = 0; j < 4; j++)
            #pragma unroll
            for (int k = 0; k < 4; k++) acc[i][j][k] = 0.0f;

    const int bm0 = blockIdx.y * 128;
    const int bn0 = blockIdx.x * 128;
    gemm_mainloop(g_fin, W1, CD, DFF, bm0, bn0, As, Bs, acc);

    const int tid = threadIdx.x;
    const int lane = tid & 31, warp = tid >> 5;
    const int wm = warp >> 2, wn = warp & 3;
    const int gid = lane >> 2, tig = lane & 3;
    #pragma unroll
    for (int mi = 0; mi < 4; mi++) {
        int r0 = bm0 + wm*64 + mi*16 + gid;
        #pragma unroll
        for (int ni = 0; ni < 4; ni++) {
            int c = bn0 + wn*32 + ni*8 + tig*2;
            float2 bv = *(const float2*)(b1 + c);
            float2 v0, v1;
            v0.x = gelu_tanh(acc[mi][ni][0] + bv.x);
            v0.y = gelu_tanh(acc[mi][ni][1] + bv.y);
            v1.x = gelu_tanh(acc[mi][ni][2] + bv.x);
            v1.y = gelu_tanh(acc[mi][ni][3] + bv.y);
            *(float2*)(g_hidden + (size_t)r0 * DFF + c) = v0;
            *(float2*)(g_hidden + (size_t)(r0 + 8) * DFF + c) = v1;
        }
    }
}

__device__ __forceinline__ void epi2_row(float* __restrict__ out, int r, int c,
                                         float f0, float f1, float4 hp) {
    float hv[4] = {hp.x, hp.y, hp.z, hp.w};
    #pragma unroll
    for (int m = 0; m < 4; m++) {
        float2* p = (float2*)(out + ((size_t)r * 4 + m) * CD + c);
        float2 o = *p;
        o.x = fmaf(hv[m], f0, o.x);
        o.y = fmaf(hv[m], f1, o.y);
        *p = o;
    }
}

// GEMM2: out[b,m,:] += hpost[b,m] * (hidden @ W2 + b2)   M=4096, N=2048, K=8192
__global__ __launch_bounds__(256) void gemm2_kernel(
    const float* __restrict__ W2, const float* __restrict__ b2,
    float* __restrict__ out)
{
    __shared__ __align__(16) uint32_t As[128 * PA];
    __shared__ __align__(16) uint32_t Bs[32 * PB];
    float acc[4][4][4];
    #pragma unroll
    for (int i = 0; i < 4; i++)
        #pragma unroll
        for (int j = 0; j < 4; j++)
            #pragma unroll
            for (int k = 0; k < 4; k++) acc[i][j][k] = 0.0f;

    const int bm0 = blockIdx.y * 128;
    const int bn0 = blockIdx.x * 128;
    gemm_mainloop(g_hidden, W2, DFF, CD, bm0, bn0, As, Bs, acc);

    const int tid = threadIdx.x;
    const int lane = tid & 31, warp = tid >> 5;
    const int wm = warp >> 2, wn = warp & 3;
    const int gid = lane >> 2, tig = lane & 3;
    #pragma unroll
    for (int mi = 0; mi < 4; mi++) {
        int r0 = bm0 + wm*64 + mi*16 + gid;
        int r1 = r0 + 8;
        float4 hp0 = *(const float4*)(g_hpost + r0 * 4);
        float4 hp1 = *(const float4*)(g_hpost + r1 * 4);
        #pragma unroll
        for (int ni = 0; ni < 4; ni++) {
            int c = bn0 + wn*32 + ni*8 + tig*2;
            float2 bv = *(const float2*)(b2 + c);
            float f00 = acc[mi][ni][0] + bv.x;
            float f01 = acc[mi][ni][1] + bv.y;
            float f10 = acc[mi][ni][2] + bv.x;
            float f11 = acc[mi][ni][3] + bv.y;
            epi2_row(out, r0, c, f00, f01, hp0);
            epi2_row(out, r1, c, f10, f11, hp1);
        }
    }
}

// ---------------------------------------------------------------- launch
extern "C" void kernel_launch(void* const* d_in, const int* in_sizes, int n_in,
                              void* d_out, int out_size) {
    (void)in_sizes; (void)n_in; (void)out_size;
    const float* x         = (const float*)d_in[0];
    const float* phi_pre   = (const float*)d_in[1];
    const float* phi_post  = (const float*)d_in[2];
    const float* phi_res   = (const float*)d_in[3];
    const float* bias_pre  = (const float*)d_in[4];
    const float* bias_post = (const float*)d_in[5];
    const float* bias_res  = (const float*)d_in[6];
    const float* alpha_pre = (const float*)d_in[7];
    const float* alpha_post= (const float*)d_in[8];
    const float* alpha_res = (const float*)d_in[9];
    const float* W1        = (const float*)d_in[10];
    const float* b1        = (const float*)d_in[11];
    const float* W2        = (const float*)d_in[12];
    const float* b2        = (const float*)d_in[13];
    float* out = (float*)d_out;

    gates_kernel<<<BR, 256>>>(x, phi_pre, phi_post, phi_res, bias_pre, bias_post,
                              bias_res, alpha_pre, alpha_post, alpha_res, out);
    gemm1_kernel<<<dim3(DFF / 128, BR / 128), 256>>>(W1, b1);
    gemm2_kernel<<<dim3(CD / 128, BR / 128), 256>>>(W2, b2, out);
}

// round 3
// speedup vs baseline: 1.0224x; 1.0224x over previous
#include <cuda_runtime.h>
#include <cstdint>

#define NS 4
#define CD 2048
#define FLT 8192
#define BR 4096
#define DFF 8192

// ---------------------------------------------------------------- scratch
__device__ float g_fin[(size_t)BR * CD];        // (B, C)    32 MB
__device__ float g_hidden[(size_t)BR * DFF];    // (B, DFF) 128 MB
__device__ float g_hpost[BR * NS];              // (B, 4)

// ---------------------------------------------------------------- helpers
__device__ __forceinline__ float fast_tanhf(float u) {
    float e = __expf(2.0f * u);
    return 1.0f - __fdividef(2.0f, e + 1.0f);
}
__device__ __forceinline__ float gelu_tanh(float x) {
    float u = 0.7978845608028654f * fmaf(0.044715f * x, x * x, x);
    return 0.5f * x * (1.0f + fast_tanhf(u));
}
__device__ __forceinline__ uint32_t f2tf32(float x) {
    uint32_t u;
    asm("cvt.rna.tf32.f32 %0, %1;" : "=r"(u) : "f"(x));
    return u;
}
__device__ __forceinline__ uint32_t smem_u32(const void* p) {
    uint32_t a;
    asm("{ .reg .u64 t; cvta.to.shared.u64 t, %1; cvt.u32.u64 %0, t; }" : "=r"(a) : "l"(p));
    return a;
}
__device__ __forceinline__ void cp16(uint32_t dst, const void* src) {
    asm volatile("cp.async.cg.shared.global [%0], [%1], 16;" :: "r"(dst), "l"(src));
}
__device__ __forceinline__ void cp_commit() {
    asm volatile("cp.async.commit_group;" ::: "memory");
}
template <int N>
__device__ __forceinline__ void cp_wait() {
    asm volatile("cp.async.wait_group %0;" :: "n"(N) : "memory");
}

// ---------------------------------------------------------------- gates (unchanged from R1)
__global__ __launch_bounds__(256) void gates_kernel(
    const float* __restrict__ x,
    const float* __restrict__ phi_pre,
    const float* __restrict__ phi_post,
    const float* __restrict__ phi_res,
    const float* __restrict__ bias_pre,
    const float* __restrict__ bias_post,
    const float* __restrict__ bias_res,
    const float* __restrict__ alpha_pre_p,
    const float* __restrict__ alpha_post_p,
    const float* __restrict__ alpha_res_p,
    float* __restrict__ out)
{
    __shared__ float sx[FLT];
    __shared__ float sred[8][25];
    __shared__ float sdot[25];
    __shared__ float sg[20];

    const int tid = threadIdx.x;
    const int b = blockIdx.x;

    const float4* xr = (const float4*)(x + (size_t)b * FLT);
    float4* sx4 = (float4*)sx;
    #pragma unroll 4
    for (int i = tid; i < FLT / 4; i += 256) sx4[i] = xr[i];
    __syncthreads();

    float acc[25];
    #pragma unroll
    for (int j = 0; j < 25; j++) acc[j] = 0.0f;

    const float4* pp4 = (const float4*)phi_pre;
    const float4* pq4 = (const float4*)phi_post;
    const float4* pr4 = (const float4*)phi_res;

    for (int f = tid; f < FLT; f += 256) {
        float xv = sx[f];
        acc[24] = fmaf(xv, xv, acc[24]);
        float4 p = pp4[f];
        acc[0] = fmaf(xv, p.x, acc[0]);
        acc[1] = fmaf(xv, p.y, acc[1]);
        acc[2] = fmaf(xv, p.z, acc[2]);
        acc[3] = fmaf(xv, p.w, acc[3]);
        float4 q = pq4[f];
        acc[4] = fmaf(xv, q.x, acc[4]);
        acc[5] = fmaf(xv, q.y, acc[5]);
        acc[6] = fmaf(xv, q.z, acc[6]);
        acc[7] = fmaf(xv, q.w, acc[7]);
        #pragma unroll
        for (int r = 0; r < 4; r++) {
            float4 rr = pr4[f * 4 + r];
            acc[8 + r*4 + 0] = fmaf(xv, rr.x, acc[8 + r*4 + 0]);
            acc[8 + r*4 + 1] = fmaf(xv, rr.y, acc[8 + r*4 + 1]);
            acc[8 + r*4 + 2] = fmaf(xv, rr.z, acc[8 + r*4 + 2]);
            acc[8 + r*4 + 3] = fmaf(xv, rr.w, acc[8 + r*4 + 3]);
        }
    }

    const int lane = tid & 31, warp = tid >> 5;
    #pragma unroll
    for (int j = 0; j < 25; j++) {
        float v = acc[j];
        v += __shfl_xor_sync(0xffffffffu, v, 16);
        v += __shfl_xor_sync(0xffffffffu, v, 8);
        v += __shfl_xor_sync(0xffffffffu, v, 4);
        v += __shfl_xor_sync(0xffffffffu, v, 2);
        v += __shfl_xor_sync(0xffffffffu, v, 1);
        if (lane == 0) sred[warp][j] = v;
    }
    __syncthreads();
    if (tid < 25) {
        float s = 0.0f;
        #pragma unroll
        for (int w = 0; w < 8; w++) s += sred[w][tid];
        sdot[tid] = s;
    }
    __syncthreads();
    if (tid == 0) {
        float inv_rms = rsqrtf(sdot[24] * (1.0f / (float)FLT) + 1e-8f);
        float a_pre = alpha_pre_p[0], a_post = alpha_post_p[0], a_res = alpha_res_p[0];
        #pragma unroll
        for (int n = 0; n < 4; n++) {
            float tpre = fmaf(a_pre, sdot[n] * inv_rms, bias_pre[n]);
            sg[n] = 1.0f / (1.0f + expf(-tpre));
            float tpost = fmaf(a_post, sdot[4 + n] * inv_rms, bias_post[n]);
            g_hpost[b * 4 + n] = 2.0f / (1.0f + expf(-tpost));
        }
        float M[4][4];
        #pragma unroll
        for (int m = 0; m < 4; m++)
            #pragma unroll
            for (int n = 0; n < 4; n++)
                M[m][n] = expf(fmaf(a_res, sdot[8 + m*4 + n] * inv_rms, bias_res[m*4 + n]));
        #pragma unroll 1
        for (int it = 0; it < 20; it++) {
            #pragma unroll
            for (int m = 0; m < 4; m++) {
                float rs = M[m][0] + M[m][1] + M[m][2] + M[m][3] + 1e-12f;
                float inv = 1.0f / rs;
                M[m][0] *= inv; M[m][1] *= inv; M[m][2] *= inv; M[m][3] *= inv;
            }
            #pragma unroll
            for (int n = 0; n < 4; n++) {
                float cs = M[0][n] + M[1][n] + M[2][n] + M[3][n] + 1e-12f;
                float inv = 1.0f / cs;
                M[0][n] *= inv; M[1][n] *= inv; M[2][n] *= inv; M[3][n] *= inv;
            }
        }
        #pragma unroll
        for (int m = 0; m < 4; m++)
            #pragma unroll
            for (int n = 0; n < 4; n++)
                sg[4 + m*4 + n] = M[m][n];
    }
    __syncthreads();

    const float h0 = sg[0], h1 = sg[1], h2 = sg[2], h3 = sg[3];
    float R[4][4];
    #pragma unroll
    for (int m = 0; m < 4; m++)
        #pragma unroll
        for (int n = 0; n < 4; n++)
            R[m][n] = sg[4 + m*4 + n];

    float4* fin4 = (float4*)(g_fin + (size_t)b * CD);
    #pragma unroll 1
    for (int c = tid; c < CD / 4; c += 256) {
        float4 x0 = sx4[c];
        float4 x1 = sx4[512 + c];
        float4 x2 = sx4[1024 + c];
        float4 x3 = sx4[1536 + c];
        float4 fv;
        fv.x = h0*x0.x + h1*x1.x + h2*x2.x + h3*x3.x;
        fv.y = h0*x0.y + h1*x1.y + h2*x2.y + h3*x3.y;
        fv.z = h0*x0.z + h1*x1.z + h2*x2.z + h3*x3.z;
        fv.w = h0*x0.w + h1*x1.w + h2*x2.w + h3*x3.w;
        fin4[c] = fv;
        #pragma unroll
        for (int m = 0; m < 4; m++) {
            float4 ov;
            ov.x = R[m][0]*x0.x + R[m][1]*x1.x + R[m][2]*x2.x + R[m][3]*x3.x;
            ov.y = R[m][0]*x0.y + R[m][1]*x1.y + R[m][2]*x2.y + R[m][3]*x3.y;
            ov.z = R[m][0]*x0.z + R[m][1]*x1.z + R[m][2]*x2.z + R[m][3]*x3.z;
            ov.w = R[m][0]*x0.w + R[m][1]*x1.w + R[m][2]*x2.w + R[m][3]*x3.w;
            ((float4*)(out + ((size_t)b * 4 + m) * CD))[c] = ov;
        }
    }
}

// ---------------------------------------------------------------- tf32 GEMM (mma.sync, cp.async 3-stage)
// Block tile 128x256, BK=32, 256 threads = 8 warps (2x4), warp tile 64x64.
// A smem: [128][PA=36] fp32, B smem: [32][PB=264] fp32. tf32 cvt on fragments.
#define STAGES 3
#define BKK 32
#define GBM 128
#define GBN 256
#define PA 36
#define PB 264
#define A_STG (GBM * PA)          // 4608 floats = 18432 B
#define B_STG (BKK * PB)          // 8448 floats = 33792 B
#define SMEM_GEMM ((STAGES * (A_STG + B_STG)) * 4)   // 156672 B

__device__ __forceinline__ void issue_chunk(
    const float* __restrict__ A, const float* __restrict__ Bm,
    int KDIM, int NDIM, int bm0, int bn0, int kt,
    uint32_t smA, uint32_t smB, int tid)
{
    #pragma unroll
    for (int q = 0; q < 4; q++) {
        int idx = q * 256 + tid;
        int row = idx >> 3;
        int c4 = idx & 7;
        cp16(smA + (row * PA + c4 * 4) * 4,
             A + (size_t)(bm0 + row) * KDIM + kt + c4 * 4);
    }
    #pragma unroll
    for (int q = 0; q < 8; q++) {
        int idx = q * 256 + tid;
        int row = idx >> 6;
        int c4 = idx & 63;
        cp16(smB + (row * PB + c4 * 4) * 4,
             Bm + (size_t)(kt + row) * NDIM + bn0 + c4 * 4);
    }
}

__device__ __forceinline__ void compute_chunk(
    const float* __restrict__ sA, const float* __restrict__ sB,
    int wm, int wn, int gid, int tig, float acc[4][8][4])
{
    #pragma unroll
    for (int kk = 0; kk < 4; kk++) {
        const int k0 = kk * 8;
        uint32_t af[4][4];
        #pragma unroll
        for (int mi = 0; mi < 4; mi++) {
            const float* ap = sA + (wm*64 + mi*16 + gid) * PA + k0 + tig;
            af[mi][0] = f2tf32(ap[0]);
            af[mi][1] = f2tf32(ap[8 * PA]);
            af[mi][2] = f2tf32(ap[4]);
            af[mi][3] = f2tf32(ap[8 * PA + 4]);
        }
        uint32_t bf[8][2];
        #pragma unroll
        for (int ni = 0; ni < 8; ni++) {
            const float* bp = sB + (k0 + tig) * PB + wn*64 + ni*8 + gid;
            bf[ni][0] = f2tf32(bp[0]);
            bf[ni][1] = f2tf32(bp[4 * PB]);
        }
        #pragma unroll
        for (int mi = 0; mi < 4; mi++)
            #pragma unroll
            for (int ni = 0; ni < 8; ni++)
                asm volatile(
                    "mma.sync.aligned.m16n8k8.row.col.f32.tf32.tf32.f32 "
                    "{%0,%1,%2,%3}, {%4,%5,%6,%7}, {%8,%9}, {%0,%1,%2,%3};\n"
                    : "+f"(acc[mi][ni][0]), "+f"(acc[mi][ni][1]),
                      "+f"(acc[mi][ni][2]), "+f"(acc[mi][ni][3])
                    : "r"(af[mi][0]), "r"(af[mi][1]), "r"(af[mi][2]), "r"(af[mi][3]),
                      "r"(bf[ni][0]), "r"(bf[ni][1]));
    }
}

__device__ __forceinline__ void gemm_mainloop(
    const float* __restrict__ A, const float* __restrict__ Bm,
    int KDIM, int NDIM, int bm0, int bn0,
    float* sm, float acc[4][8][4])
{
    const int tid = threadIdx.x;
    const int lane = tid & 31, wid = tid >> 5;
    const int wm = wid >> 2, wn = wid & 3;
    const int gid = lane >> 2, tig = lane & 3;

    float* sA = sm;                       // STAGES * A_STG
    float* sB = sm + STAGES * A_STG;      // STAGES * B_STG
    const uint32_t sAu = smem_u32(sA);
    const uint32_t sBu = smem_u32(sB);

    const int nch = KDIM / BKK;

    #pragma unroll
    for (int i = 0; i < STAGES; i++) {
        issue_chunk(A, Bm, KDIM, NDIM, bm0, bn0, i * BKK,
                    sAu + i * A_STG * 4, sBu + i * B_STG * 4, tid);
        cp_commit();
    }

    for (int i = 0; i < nch; i++) {
        const int s = i % STAGES;
        cp_wait<STAGES - 1>();
        __syncthreads();
        compute_chunk(sA + s * A_STG, sB + s * B_STG, wm, wn, gid, tig, acc);
        __syncthreads();
        const int nx = i + STAGES;
        if (nx < nch)
            issue_chunk(A, Bm, KDIM, NDIM, bm0, bn0, nx * BKK,
                        sAu + s * A_STG * 4, sBu + s * B_STG * 4, tid);
        cp_commit();
    }
}

// GEMM1: g_hidden = gelu(g_fin @ W1 + b1);  M=4096, N=8192, K=2048
__global__ __launch_bounds__(256) void gemm1_kernel(
    const float* __restrict__ W1, const float* __restrict__ b1)
{
    extern __shared__ float sm[];
    float acc[4][8][4];
    #pragma unroll
    for (int i = 0; i < 4; i++)
        #pragma unroll
        for (int j = 0; j < 8; j++)
            #pragma unroll
            for (int k = 0; k < 4; k++) acc[i][j][k] = 0.0f;

    const int bm0 = blockIdx.y * GBM;
    const int bn0 = blockIdx.x * GBN;
    gemm_mainloop(g_fin, W1, CD, DFF, bm0, bn0, sm, acc);

    const int tid = threadIdx.x;
    const int lane = tid & 31, wid = tid >> 5;
    const int wm = wid >> 2, wn = wid & 3;
    const int gid = lane >> 2, tig = lane & 3;

    #pragma unroll
    for (int mi = 0; mi < 4; mi++) {
        int r0 = bm0 + wm*64 + mi*16 + gid;
        #pragma unroll
        for (int ni = 0; ni < 8; ni++) {
            int c = bn0 + wn*64 + ni*8 + tig*2;
            float2 bv = *(const float2*)(b1 + c);
            float2 v0, v1;
            v0.x = gelu_tanh(acc[mi][ni][0] + bv.x);
            v0.y = gelu_tanh(acc[mi][ni][1] + bv.y);
            v1.x = gelu_tanh(acc[mi][ni][2] + bv.x);
            v1.y = gelu_tanh(acc[mi][ni][3] + bv.y);
            *(float2*)(g_hidden + (size_t)r0 * DFF + c) = v0;
            *(float2*)(g_hidden + (size_t)(r0 + 8) * DFF + c) = v1;
        }
    }
}

__device__ __forceinline__ void epi2_row(float* __restrict__ out, int r, int c,
                                         float f0, float f1, float4 hp) {
    float hv[4] = {hp.x, hp.y, hp.z, hp.w};
    #pragma unroll
    for (int m = 0; m < 4; m++) {
        float2* p = (float2*)(out + ((size_t)r * 4 + m) * CD + c);
        float2 o = *p;
        o.x = fmaf(hv[m], f0, o.x);
        o.y = fmaf(hv[m], f1, o.y);
        *p = o;
    }
}

// GEMM2: out[b,m,:] += hpost[b,m]*(g_hidden @ W2 + b2);  M=4096, N=2048, K=8192
__global__ __launch_bounds__(256) void gemm2_kernel(
    const float* __restrict__ W2, const float* __restrict__ b2,
    float* __restrict__ out)
{
    extern __shared__ float sm[];
    float acc[4][8][4];
    #pragma unroll
    for (int i = 0; i < 4; i++)
        #pragma unroll
        for (int j = 0; j < 8; j++)
            #pragma unroll
            for (int k = 0; k < 4; k++) acc[i][j][k] = 0.0f;

    const int bm0 = blockIdx.y * GBM;
    const int bn0 = blockIdx.x * GBN;
    gemm_mainloop(g_hidden, W2, DFF, CD, bm0, bn0, sm, acc);

    const int tid = threadIdx.x;
    const int lane = tid & 31, wid = tid >> 5;
    const int wm = wid >> 2, wn = wid & 3;
    const int gid = lane >> 2, tig = lane & 3;

    #pragma unroll
    for (int mi = 0; mi < 4; mi++) {
        int r0 = bm0 + wm*64 + mi*16 + gid;
        int r1 = r0 + 8;
        float4 hp0 = *(const float4*)(g_hpost + r0 * 4);
        float4 hp1 = *(const float4*)(g_hpost + r1 * 4);
        #pragma unroll
        for (int ni = 0; ni < 8; ni++) {
            int c = bn0 + wn*64 + ni*8 + tig*2;
            float2 bv = *(const float2*)(b2 + c);
            epi2_row(out, r0, c, acc[mi][ni][0] + bv.x, acc[mi][ni][1] + bv.y, hp0);
            epi2_row(out, r1, c, acc[mi][ni][2] + bv.x, acc[mi][ni][3] + bv.y, hp1);
        }
    }
}

// ---------------------------------------------------------------- launch
extern "C" void kernel_launch(void* const* d_in, const int* in_sizes, int n_in,
                              void* d_out, int out_size) {
    (void)in_sizes; (void)n_in; (void)out_size;
    const float* x         = (const float*)d_in[0];
    const float* phi_pre   = (const float*)d_in[1];
    const float* phi_post  = (const float*)d_in[2];
    const float* phi_res   = (const float*)d_in[3];
    const float* bias_pre  = (const float*)d_in[4];
    const float* bias_post = (const float*)d_in[5];
    const float* bias_res  = (const float*)d_in[6];
    const float* alpha_pre = (const float*)d_in[7];
    const float* alpha_post= (const float*)d_in[8];
    const float* alpha_res = (const float*)d_in[9];
    const float* W1        = (const float*)d_in[10];
    const float* b1        = (const float*)d_in[11];
    const float* W2        = (const float*)d_in[12];
    const float* b2        = (const float*)d_in[13];
    float* out = (float*)d_out;

    static bool configured = false;
    if (!configured) {
        cudaFuncSetAttribute(gemm1_kernel, cudaFuncAttributeMaxDynamicSharedMemorySize, SMEM_GEMM);
        cudaFuncSetAttribute(gemm2_kernel, cudaFuncAttributeMaxDynamicSharedMemorySize, SMEM_GEMM);
        configured = true;
    }

    gates_kernel<<<BR, 256>>>(x, phi_pre, phi_post, phi_res, bias_pre, bias_post,
                              bias_res, alpha_pre, alpha_post, alpha_res, out);

    gemm1_kernel<<<dim3(DFF / GBN, BR / GBM), 256, SMEM_GEMM>>>(W1, b1);
    gemm2_kernel<<<dim3(CD / GBN, BR / GBM), 256, SMEM_GEMM>>>(W2, b2, out);
}

// round 4
// speedup vs baseline: 1.1247x; 1.1001x over previous
#include <cuda_runtime.h>
#include <cstdint>

#define NS 4
#define CD 2048
#define FLT 8192
#define BR 4096
#define DFF 8192

// ---------------------------------------------------------------- scratch
__device__ float g_fin[(size_t)BR * CD];        // (B, C)    32 MB  (tf32-rounded)
__device__ float g_hidden[(size_t)BR * DFF];    // (B, DFF) 128 MB  (tf32-rounded)
__device__ float g_hpost[BR * NS];              // (B, 4)
__device__ float g_w1r[(size_t)CD * DFF];       // W1 rounded  64 MB
__device__ float g_w2r[(size_t)DFF * CD];       // W2 rounded  64 MB

// ---------------------------------------------------------------- helpers
__device__ __forceinline__ float fast_tanhf(float u) {
    float e = __expf(2.0f * u);
    return 1.0f - __fdividef(2.0f, e + 1.0f);
}
__device__ __forceinline__ float gelu_tanh(float x) {
    float u = 0.7978845608028654f * fmaf(0.044715f * x, x * x, x);
    return 0.5f * x * (1.0f + fast_tanhf(u));
}
__device__ __forceinline__ uint32_t f2tf32(float x) {
    uint32_t u;
    asm("cvt.rna.tf32.f32 %0, %1;" : "=r"(u) : "f"(x));
    return u;
}
__device__ __forceinline__ float roundtf(float x) { return __uint_as_float(f2tf32(x)); }
__device__ __forceinline__ uint32_t smem_u32(const void* p) {
    uint32_t a;
    asm("{ .reg .u64 t; cvta.to.shared.u64 t, %1; cvt.u32.u64 %0, t; }" : "=r"(a) : "l"(p));
    return a;
}
__device__ __forceinline__ void cp16(uint32_t dst, const void* src) {
    asm volatile("cp.async.cg.shared.global [%0], [%1], 16;" :: "r"(dst), "l"(src));
}
__device__ __forceinline__ void cp_commit() {
    asm volatile("cp.async.commit_group;" ::: "memory");
}
template <int N>
__device__ __forceinline__ void cp_wait() {
    asm volatile("cp.async.wait_group %0;" :: "n"(N) : "memory");
}

// ---------------------------------------------------------------- weight prep (tf32 round)
__global__ __launch_bounds__(256) void round_kernel(
    const float* __restrict__ src, float* __restrict__ dst, int n4)
{
    int i = blockIdx.x * 256 + threadIdx.x;
    if (i < n4) {
        float4 v = ((const float4*)src)[i];
        v.x = roundtf(v.x); v.y = roundtf(v.y);
        v.z = roundtf(v.z); v.w = roundtf(v.w);
        ((float4*)dst)[i] = v;
    }
}

// ---------------------------------------------------------------- gates (2 rows/block)
__global__ __launch_bounds__(256) void gates_kernel(
    const float* __restrict__ x,
    const float* __restrict__ phi_pre,
    const float* __restrict__ phi_post,
    const float* __restrict__ phi_res,
    const float* __restrict__ bias_pre,
    const float* __restrict__ bias_post,
    const float* __restrict__ bias_res,
    const float* __restrict__ alpha_pre_p,
    const float* __restrict__ alpha_post_p,
    const float* __restrict__ alpha_res_p,
    float* __restrict__ out)
{
    extern __shared__ float sx[];           // 2 * FLT floats (64 KB)
    __shared__ float sred[8][50];
    __shared__ float sdot[50];
    __shared__ float sg[2][20];             // [row][0..3]=Hpre, [row][4..19]=Hres

    const int tid = threadIdx.x;
    const int b0 = blockIdx.x * 2;

    const float4* xr = (const float4*)(x + (size_t)b0 * FLT);
    float4* sx4 = (float4*)sx;
    #pragma unroll 4
    for (int i = tid; i < 2 * FLT / 4; i += 256) sx4[i] = xr[i];
    __syncthreads();

    float acc[50];
    #pragma unroll
    for (int j = 0; j < 50; j++) acc[j] = 0.0f;

    const float4* pp4 = (const float4*)phi_pre;
    const float4* pq4 = (const float4*)phi_post;
    const float4* pr4 = (const float4*)phi_res;

    for (int f = tid; f < FLT; f += 256) {
        float xv0 = sx[f];
        float xv1 = sx[FLT + f];
        acc[24] = fmaf(xv0, xv0, acc[24]);
        acc[49] = fmaf(xv1, xv1, acc[49]);
        float4 p = pp4[f];
        acc[0] = fmaf(xv0, p.x, acc[0]);   acc[25] = fmaf(xv1, p.x, acc[25]);
        acc[1] = fmaf(xv0, p.y, acc[1]);   acc[26] = fmaf(xv1, p.y, acc[26]);
        acc[2] = fmaf(xv0, p.z, acc[2]);   acc[27] = fmaf(xv1, p.z, acc[27]);
        acc[3] = fmaf(xv0, p.w, acc[3]);   acc[28] = fmaf(xv1, p.w, acc[28]);
        float4 q = pq4[f];
        acc[4] = fmaf(xv0, q.x, acc[4]);   acc[29] = fmaf(xv1, q.x, acc[29]);
        acc[5] = fmaf(xv0, q.y, acc[5]);   acc[30] = fmaf(xv1, q.y, acc[30]);
        acc[6] = fmaf(xv0, q.z, acc[6]);   acc[31] = fmaf(xv1, q.z, acc[31]);
        acc[7] = fmaf(xv0, q.w, acc[7]);   acc[32] = fmaf(xv1, q.w, acc[32]);
        #pragma unroll
        for (int r = 0; r < 4; r++) {
            float4 rr = pr4[f * 4 + r];
            acc[8 + r*4 + 0] = fmaf(xv0, rr.x, acc[8 + r*4 + 0]);
            acc[8 + r*4 + 1] = fmaf(xv0, rr.y, acc[8 + r*4 + 1]);
            acc[8 + r*4 + 2] = fmaf(xv0, rr.z, acc[8 + r*4 + 2]);
            acc[8 + r*4 + 3] = fmaf(xv0, rr.w, acc[8 + r*4 + 3]);
            acc[33 + r*4 + 0] = fmaf(xv1, rr.x, acc[33 + r*4 + 0]);
            acc[33 + r*4 + 1] = fmaf(xv1, rr.y, acc[33 + r*4 + 1]);
            acc[33 + r*4 + 2] = fmaf(xv1, rr.z, acc[33 + r*4 + 2]);
            acc[33 + r*4 + 3] = fmaf(xv1, rr.w, acc[33 + r*4 + 3]);
        }
    }

    const int lane = tid & 31, warp = tid >> 5;
    #pragma unroll
    for (int j = 0; j < 50; j++) {
        float v = acc[j];
        v += __shfl_xor_sync(0xffffffffu, v, 16);
        v += __shfl_xor_sync(0xffffffffu, v, 8);
        v += __shfl_xor_sync(0xffffffffu, v, 4);
        v += __shfl_xor_sync(0xffffffffu, v, 2);
        v += __shfl_xor_sync(0xffffffffu, v, 1);
        if (lane == 0) sred[warp][j] = v;
    }
    __syncthreads();
    if (tid < 50) {
        float s = 0.0f;
        #pragma unroll
        for (int w = 0; w < 8; w++) s += sred[w][tid];
        sdot[tid] = s;
    }
    __syncthreads();
    if (tid < 2) {
        const int rowoff = tid * 25;
        const int b = b0 + tid;
        float inv_rms = rsqrtf(sdot[rowoff + 24] * (1.0f / (float)FLT) + 1e-8f);
        float a_pre = alpha_pre_p[0], a_post = alpha_post_p[0], a_res = alpha_res_p[0];
        #pragma unroll
        for (int n = 0; n < 4; n++) {
            float tpre = fmaf(a_pre, sdot[rowoff + n] * inv_rms, bias_pre[n]);
            sg[tid][n] = 1.0f / (1.0f + expf(-tpre));
            float tpost = fmaf(a_post, sdot[rowoff + 4 + n] * inv_rms, bias_post[n]);
            g_hpost[b * 4 + n] = 2.0f / (1.0f + expf(-tpost));
        }
        float M[4][4];
        #pragma unroll
        for (int m = 0; m < 4; m++)
            #pragma unroll
            for (int n = 0; n < 4; n++)
                M[m][n] = expf(fmaf(a_res, sdot[rowoff + 8 + m*4 + n] * inv_rms, bias_res[m*4 + n]));
        #pragma unroll 1
        for (int it = 0; it < 20; it++) {
            #pragma unroll
            for (int m = 0; m < 4; m++) {
                float rs = M[m][0] + M[m][1] + M[m][2] + M[m][3] + 1e-12f;
                float inv = 1.0f / rs;
                M[m][0] *= inv; M[m][1] *= inv; M[m][2] *= inv; M[m][3] *= inv;
            }
            #pragma unroll
            for (int n = 0; n < 4; n++) {
                float cs = M[0][n] + M[1][n] + M[2][n] + M[3][n] + 1e-12f;
                float inv = 1.0f / cs;
                M[0][n] *= inv; M[1][n] *= inv; M[2][n] *= inv; M[3][n] *= inv;
            }
        }
        #pragma unroll
        for (int m = 0; m < 4; m++)
            #pragma unroll
            for (int n = 0; n < 4; n++)
                sg[tid][4 + m*4 + n] = M[m][n];
    }
    __syncthreads();

    #pragma unroll
    for (int r = 0; r < 2; r++) {
        const int b = b0 + r;
        const float h0 = sg[r][0], h1 = sg[r][1], h2 = sg[r][2], h3 = sg[r][3];
        float R[4][4];
        #pragma unroll
        for (int m = 0; m < 4; m++)
            #pragma unroll
            for (int n = 0; n < 4; n++)
                R[m][n] = sg[r][4 + m*4 + n];

        const float4* sxr = sx4 + r * (FLT / 4);
        float4* fin4 = (float4*)(g_fin + (size_t)b * CD);
        #pragma unroll 1
        for (int c = tid; c < CD / 4; c += 256) {
            float4 x0 = sxr[c];
            float4 x1 = sxr[512 + c];
            float4 x2 = sxr[1024 + c];
            float4 x3 = sxr[1536 + c];
            float4 fv;
            fv.x = roundtf(h0*x0.x + h1*x1.x + h2*x2.x + h3*x3.x);
            fv.y = roundtf(h0*x0.y + h1*x1.y + h2*x2.y + h3*x3.y);
            fv.z = roundtf(h0*x0.z + h1*x1.z + h2*x2.z + h3*x3.z);
            fv.w = roundtf(h0*x0.w + h1*x1.w + h2*x2.w + h3*x3.w);
            fin4[c] = fv;
            #pragma unroll
            for (int m = 0; m < 4; m++) {
                float4 ov;
                ov.x = R[m][0]*x0.x + R[m][1]*x1.x + R[m][2]*x2.x + R[m][3]*x3.x;
                ov.y = R[m][0]*x0.y + R[m][1]*x1.y + R[m][2]*x2.y + R[m][3]*x3.y;
                ov.z = R[m][0]*x0.z + R[m][1]*x1.z + R[m][2]*x2.z + R[m][3]*x3.z;
                ov.w = R[m][0]*x0.w + R[m][1]*x1.w + R[m][2]*x2.w + R[m][3]*x3.w;
                ((float4*)(out + ((size_t)b * 4 + m) * CD))[c] = ov;
            }
        }
    }
}

// ---------------------------------------------------------------- tf32 GEMM (no in-loop cvt)
#define STAGES 3
#define BKK 32
#define GBM 128
#define GBN 256
#define PA 36
#define PB 264
#define A_STG (GBM * PA)
#define B_STG (BKK * PB)
#define SMEM_GEMM ((STAGES * (A_STG + B_STG)) * 4)   // 156672 B

__device__ __forceinline__ void issue_chunk(
    const float* __restrict__ A, const float* __restrict__ Bm,
    int KDIM, int NDIM, int bm0, int bn0, int kt,
    uint32_t smA, uint32_t smB, int tid)
{
    #pragma unroll
    for (int q = 0; q < 4; q++) {
        int idx = q * 256 + tid;
        int row = idx >> 3;
        int c4 = idx & 7;
        cp16(smA + (row * PA + c4 * 4) * 4,
             A + (size_t)(bm0 + row) * KDIM + kt + c4 * 4);
    }
    #pragma unroll
    for (int q = 0; q < 8; q++) {
        int idx = q * 256 + tid;
        int row = idx >> 6;
        int c4 = idx & 63;
        cp16(smB + (row * PB + c4 * 4) * 4,
             Bm + (size_t)(kt + row) * NDIM + bn0 + c4 * 4);
    }
}

__device__ __forceinline__ void compute_chunk(
    const uint32_t* __restrict__ sA, const uint32_t* __restrict__ sB,
    int wm, int wn, int gid, int tig, float acc[4][8][4])
{
    #pragma unroll
    for (int kk = 0; kk < 4; kk++) {
        const int k0 = kk * 8;
        uint32_t af[4][4];
        #pragma unroll
        for (int mi = 0; mi < 4; mi++) {
            const uint32_t* ap = sA + (wm*64 + mi*16 + gid) * PA + k0 + tig;
            af[mi][0] = ap[0];
            af[mi][1] = ap[8 * PA];
            af[mi][2] = ap[4];
            af[mi][3] = ap[8 * PA + 4];
        }
        uint32_t bf[8][2];
        #pragma unroll
        for (int ni = 0; ni < 8; ni++) {
            const uint32_t* bp = sB + (k0 + tig) * PB + wn*64 + ni*8 + gid;
            bf[ni][0] = bp[0];
            bf[ni][1] = bp[4 * PB];
        }
        #pragma unroll
        for (int mi = 0; mi < 4; mi++)
            #pragma unroll
            for (int ni = 0; ni < 8; ni++)
                asm volatile(
                    "mma.sync.aligned.m16n8k8.row.col.f32.tf32.tf32.f32 "
                    "{%0,%1,%2,%3}, {%4,%5,%6,%7}, {%8,%9}, {%0,%1,%2,%3};\n"
                    : "+f"(acc[mi][ni][0]), "+f"(acc[mi][ni][1]),
                      "+f"(acc[mi][ni][2]), "+f"(acc[mi][ni][3])
                    : "r"(af[mi][0]), "r"(af[mi][1]), "r"(af[mi][2]), "r"(af[mi][3]),
                      "r"(bf[ni][0]), "r"(bf[ni][1]));
    }
}

__device__ __forceinline__ void gemm_mainloop(
    const float* __restrict__ A, const float* __restrict__ Bm,
    int KDIM, int NDIM, int bm0, int bn0,
    float* sm, float acc[4][8][4])
{
    const int tid = threadIdx.x;
    const int lane = tid & 31, wid = tid >> 5;
    const int wm = wid >> 2, wn = wid & 3;
    const int gid = lane >> 2, tig = lane & 3;

    float* sA = sm;
    float* sB = sm + STAGES * A_STG;
    const uint32_t sAu = smem_u32(sA);
    const uint32_t sBu = smem_u32(sB);

    const int nch = KDIM / BKK;

    #pragma unroll
    for (int i = 0; i < STAGES; i++) {
        issue_chunk(A, Bm, KDIM, NDIM, bm0, bn0, i * BKK,
                    sAu + i * A_STG * 4, sBu + i * B_STG * 4, tid);
        cp_commit();
    }

    for (int i = 0; i < nch; i++) {
        const int s = i % STAGES;
        cp_wait<STAGES - 1>();
        __syncthreads();
        compute_chunk((const uint32_t*)(sA + s * A_STG),
                      (const uint32_t*)(sB + s * B_STG), wm, wn, gid, tig, acc);
        __syncthreads();
        const int nx = i + STAGES;
        if (nx < nch)
            issue_chunk(A, Bm, KDIM, NDIM, bm0, bn0, nx * BKK,
                        sAu + s * A_STG * 4, sBu + s * B_STG * 4, tid);
        cp_commit();
    }
}

// GEMM1: g_hidden = round_tf32(gelu(g_fin @ W1r + b1));  M=4096, N=8192, K=2048
__global__ __launch_bounds__(256) void gemm1_kernel(const float* __restrict__ b1)
{
    extern __shared__ float sm[];
    float acc[4][8][4];
    #pragma unroll
    for (int i = 0; i < 4; i++)
        #pragma unroll
        for (int j = 0; j < 8; j++)
            #pragma unroll
            for (int k = 0; k < 4; k++) acc[i][j][k] = 0.0f;

    const int bm0 = blockIdx.y * GBM;
    const int bn0 = blockIdx.x * GBN;
    gemm_mainloop(g_fin, g_w1r, CD, DFF, bm0, bn0, sm, acc);

    const int tid = threadIdx.x;
    const int lane = tid & 31, wid = tid >> 5;
    const int wm = wid >> 2, wn = wid & 3;
    const int gid = lane >> 2, tig = lane & 3;

    #pragma unroll
    for (int mi = 0; mi < 4; mi++) {
        int r0 = bm0 + wm*64 + mi*16 + gid;
        #pragma unroll
        for (int ni = 0; ni < 8; ni++) {
            int c = bn0 + wn*64 + ni*8 + tig*2;
            float2 bv = *(const float2*)(b1 + c);
            float2 v0, v1;
            v0.x = roundtf(gelu_tanh(acc[mi][ni][0] + bv.x));
            v0.y = roundtf(gelu_tanh(acc[mi][ni][1] + bv.y));
            v1.x = roundtf(gelu_tanh(acc[mi][ni][2] + bv.x));
            v1.y = roundtf(gelu_tanh(acc[mi][ni][3] + bv.y));
            *(float2*)(g_hidden + (size_t)r0 * DFF + c) = v0;
            *(float2*)(g_hidden + (size_t)(r0 + 8) * DFF + c) = v1;
        }
    }
}

__device__ __forceinline__ void epi2_row(float* __restrict__ out, int r, int c,
                                         float f0, float f1, float4 hp) {
    float hv[4] = {hp.x, hp.y, hp.z, hp.w};
    #pragma unroll
    for (int m = 0; m < 4; m++) {
        float2* p = (float2*)(out + ((size_t)r * 4 + m) * CD + c);
        float2 o = *p;
        o.x = fmaf(hv[m], f0, o.x);
        o.y = fmaf(hv[m], f1, o.y);
        *p = o;
    }
}

// GEMM2: out[b,m,:] += hpost[b,m]*(g_hidden @ W2r + b2);  M=4096, N=2048, K=8192
__global__ __launch_bounds__(256) void gemm2_kernel(
    const float* __restrict__ b2, float* __restrict__ out)
{
    extern __shared__ float sm[];
    float acc[4][8][4];
    #pragma unroll
    for (int i = 0; i < 4; i++)
        #pragma unroll
        for (int j = 0; j < 8; j++)
            #pragma unroll
            for (int k = 0; k < 4; k++) acc[i][j][k] = 0.0f;

    const int bm0 = blockIdx.y * GBM;
    const int bn0 = blockIdx.x * GBN;
    gemm_mainloop(g_hidden, g_w2r, DFF, CD, bm0, bn0, sm, acc);

    const int tid = threadIdx.x;
    const int lane = tid & 31, wid = tid >> 5;
    const int wm = wid >> 2, wn = wid & 3;
    const int gid = lane >> 2, tig = lane & 3;

    #pragma unroll
    for (int mi = 0; mi < 4; mi++) {
        int r0 = bm0 + wm*64 + mi*16 + gid;
        int r1 = r0 + 8;
        float4 hp0 = *(const float4*)(g_hpost + r0 * 4);
        float4 hp1 = *(const float4*)(g_hpost + r1 * 4);
        #pragma unroll
        for (int ni = 0; ni < 8; ni++) {
            int c = bn0 + wn*64 + ni*8 + tig*2;
            float2 bv = *(const float2*)(b2 + c);
            epi2_row(out, r0, c, acc[mi][ni][0] + bv.x, acc[mi][ni][1] + bv.y, hp0);
            epi2_row(out, r1, c, acc[mi][ni][2] + bv.x, acc[mi][ni][3] + bv.y, hp1);
        }
    }
}

// ---------------------------------------------------------------- launch
extern "C" void kernel_launch(void* const* d_in, const int* in_sizes, int n_in,
                              void* d_out, int out_size) {
    (void)in_sizes; (void)n_in; (void)out_size;
    const float* x         = (const float*)d_in[0];
    const float* phi_pre   = (const float*)d_in[1];
    const float* phi_post  = (const float*)d_in[2];
    const float* phi_res   = (const float*)d_in[3];
    const float* bias_pre  = (const float*)d_in[4];
    const float* bias_post = (const float*)d_in[5];
    const float* bias_res  = (const float*)d_in[6];
    const float* alpha_pre = (const float*)d_in[7];
    const float* alpha_post= (const float*)d_in[8];
    const float* alpha_res = (const float*)d_in[9];
    const float* W1        = (const float*)d_in[10];
    const float* b1        = (const float*)d_in[11];
    const float* W2        = (const float*)d_in[12];
    const float* b2        = (const float*)d_in[13];
    float* out = (float*)d_out;

    static float* w1r_ptr = nullptr;
    static float* w2r_ptr = nullptr;
    if (!w1r_ptr) {
        cudaGetSymbolAddress((void**)&w1r_ptr, g_w1r);
        cudaGetSymbolAddress((void**)&w2r_ptr, g_w2r);
        cudaFuncSetAttribute(gemm1_kernel, cudaFuncAttributeMaxDynamicSharedMemorySize, SMEM_GEMM);
        cudaFuncSetAttribute(gemm2_kernel, cudaFuncAttributeMaxDynamicSharedMemorySize, SMEM_GEMM);
        cudaFuncSetAttribute(gates_kernel, cudaFuncAttributeMaxDynamicSharedMemorySize, 2 * FLT * 4);
    }

    const int n4 = (CD * DFF) / 4;
    round_kernel<<<(n4 + 255) / 256, 256>>>(W1, w1r_ptr, n4);
    round_kernel<<<(n4 + 255) / 256, 256>>>(W2, w2r_ptr, n4);

    gates_kernel<<<BR / 2, 256, 2 * FLT * 4>>>(x, phi_pre, phi_post, phi_res,
                                               bias_pre, bias_post, bias_res,
                                               alpha_pre, alpha_post, alpha_res, out);

    gemm1_kernel<<<dim3(DFF / GBN, BR / GBM), 256, SMEM_GEMM>>>(b1);
    gemm2_kernel<<<dim3(CD / GBN, BR / GBM), 256, SMEM_GEMM>>>(b2, out);
}

// round 5
// speedup vs baseline: 1.2202x; 1.0849x over previous
#include <cuda_runtime.h>
#include <cstdint>

#define NS 4
#define CD 2048
#define FLT 8192
#define BR 4096
#define DFF 8192

// ---------------------------------------------------------------- scratch
__device__ float g_fin[(size_t)BR * CD];        // (B, C)    32 MB  (tf32-rounded)
__device__ float g_hidden[(size_t)BR * DFF];    // (B, DFF) 128 MB  (tf32-rounded)
__device__ float g_hpost[BR * NS];              // (B, 4)
__device__ float g_w1r[(size_t)CD * DFF];       // W1 rounded  64 MB
__device__ float g_w2r[(size_t)DFF * CD];       // W2 rounded  64 MB

// ---------------------------------------------------------------- helpers
__device__ __forceinline__ float fast_tanhf(float u) {
    float e = __expf(2.0f * u);
    return 1.0f - __fdividef(2.0f, e + 1.0f);
}
__device__ __forceinline__ float gelu_tanh(float x) {
    float u = 0.7978845608028654f * fmaf(0.044715f * x, x * x, x);
    return 0.5f * x * (1.0f + fast_tanhf(u));
}
__device__ __forceinline__ uint32_t f2tf32(float x) {
    uint32_t u;
    asm("cvt.rna.tf32.f32 %0, %1;" : "=r"(u) : "f"(x));
    return u;
}
__device__ __forceinline__ float roundtf(float x) { return __uint_as_float(f2tf32(x)); }
__device__ __forceinline__ uint32_t smem_u32(const void* p) {
    uint32_t a;
    asm("{ .reg .u64 t; cvta.to.shared.u64 t, %1; cvt.u32.u64 %0, t; }" : "=r"(a) : "l"(p));
    return a;
}
__device__ __forceinline__ void cp16(uint32_t dst, const void* src) {
    asm volatile("cp.async.cg.shared.global [%0], [%1], 16;" :: "r"(dst), "l"(src));
}
__device__ __forceinline__ void cp_commit() {
    asm volatile("cp.async.commit_group;" ::: "memory");
}
template <int N>
__device__ __forceinline__ void cp_wait() {
    asm volatile("cp.async.wait_group %0;" :: "n"(N) : "memory");
}

// ---------------------------------------------------------------- weight prep (tf32 round)
__global__ __launch_bounds__(256) void round_kernel(
    const float* __restrict__ src, float* __restrict__ dst, int n4)
{
    int i = blockIdx.x * 256 + threadIdx.x;
    if (i < n4) {
        float4 v = ((const float4*)src)[i];
        v.x = roundtf(v.x); v.y = roundtf(v.y);
        v.z = roundtf(v.z); v.w = roundtf(v.w);
        ((float4*)dst)[i] = v;
    }
}

// ---------------------------------------------------------------- gates (2 rows/block)
__global__ __launch_bounds__(256) void gates_kernel(
    const float* __restrict__ x,
    const float* __restrict__ phi_pre,
    const float* __restrict__ phi_post,
    const float* __restrict__ phi_res,
    const float* __restrict__ bias_pre,
    const float* __restrict__ bias_post,
    const float* __restrict__ bias_res,
    const float* __restrict__ alpha_pre_p,
    const float* __restrict__ alpha_post_p,
    const float* __restrict__ alpha_res_p,
    float* __restrict__ out)
{
    extern __shared__ float sx[];           // 2 * FLT floats (64 KB)
    __shared__ float sred[8][50];
    __shared__ float sdot[50];
    __shared__ float sg[2][20];

    const int tid = threadIdx.x;
    const int b0 = blockIdx.x * 2;

    const float4* xr = (const float4*)(x + (size_t)b0 * FLT);
    float4* sx4 = (float4*)sx;
    #pragma unroll 4
    for (int i = tid; i < 2 * FLT / 4; i += 256) sx4[i] = xr[i];
    __syncthreads();

    float acc[50];
    #pragma unroll
    for (int j = 0; j < 50; j++) acc[j] = 0.0f;

    const float4* pp4 = (const float4*)phi_pre;
    const float4* pq4 = (const float4*)phi_post;
    const float4* pr4 = (const float4*)phi_res;

    for (int f = tid; f < FLT; f += 256) {
        float xv0 = sx[f];
        float xv1 = sx[FLT + f];
        acc[24] = fmaf(xv0, xv0, acc[24]);
        acc[49] = fmaf(xv1, xv1, acc[49]);
        float4 p = pp4[f];
        acc[0] = fmaf(xv0, p.x, acc[0]);   acc[25] = fmaf(xv1, p.x, acc[25]);
        acc[1] = fmaf(xv0, p.y, acc[1]);   acc[26] = fmaf(xv1, p.y, acc[26]);
        acc[2] = fmaf(xv0, p.z, acc[2]);   acc[27] = fmaf(xv1, p.z, acc[27]);
        acc[3] = fmaf(xv0, p.w, acc[3]);   acc[28] = fmaf(xv1, p.w, acc[28]);
        float4 q = pq4[f];
        acc[4] = fmaf(xv0, q.x, acc[4]);   acc[29] = fmaf(xv1, q.x, acc[29]);
        acc[5] = fmaf(xv0, q.y, acc[5]);   acc[30] = fmaf(xv1, q.y, acc[30]);
        acc[6] = fmaf(xv0, q.z, acc[6]);   acc[31] = fmaf(xv1, q.z, acc[31]);
        acc[7] = fmaf(xv0, q.w, acc[7]);   acc[32] = fmaf(xv1, q.w, acc[32]);
        #pragma unroll
        for (int r = 0; r < 4; r++) {
            float4 rr = pr4[f * 4 + r];
            acc[8 + r*4 + 0] = fmaf(xv0, rr.x, acc[8 + r*4 + 0]);
            acc[8 + r*4 + 1] = fmaf(xv0, rr.y, acc[8 + r*4 + 1]);
            acc[8 + r*4 + 2] = fmaf(xv0, rr.z, acc[8 + r*4 + 2]);
            acc[8 + r*4 + 3] = fmaf(xv0, rr.w, acc[8 + r*4 + 3]);
            acc[33 + r*4 + 0] = fmaf(xv1, rr.x, acc[33 + r*4 + 0]);
            acc[33 + r*4 + 1] = fmaf(xv1, rr.y, acc[33 + r*4 + 1]);
            acc[33 + r*4 + 2] = fmaf(xv1, rr.z, acc[33 + r*4 + 2]);
            acc[33 + r*4 + 3] = fmaf(xv1, rr.w, acc[33 + r*4 + 3]);
        }
    }

    const int lane = tid & 31, warp = tid >> 5;
    #pragma unroll
    for (int j = 0; j < 50; j++) {
        float v = acc[j];
        v += __shfl_xor_sync(0xffffffffu, v, 16);
        v += __shfl_xor_sync(0xffffffffu, v, 8);
        v += __shfl_xor_sync(0xffffffffu, v, 4);
        v += __shfl_xor_sync(0xffffffffu, v, 2);
        v += __shfl_xor_sync(0xffffffffu, v, 1);
        if (lane == 0) sred[warp][j] = v;
    }
    __syncthreads();
    if (tid < 50) {
        float s = 0.0f;
        #pragma unroll
        for (int w = 0; w < 8; w++) s += sred[w][tid];
        sdot[tid] = s;
    }
    __syncthreads();
    if (tid < 2) {
        const int rowoff = tid * 25;
        const int b = b0 + tid;
        float inv_rms = rsqrtf(sdot[rowoff + 24] * (1.0f / (float)FLT) + 1e-8f);
        float a_pre = alpha_pre_p[0], a_post = alpha_post_p[0], a_res = alpha_res_p[0];
        #pragma unroll
        for (int n = 0; n < 4; n++) {
            float tpre = fmaf(a_pre, sdot[rowoff + n] * inv_rms, bias_pre[n]);
            sg[tid][n] = 1.0f / (1.0f + expf(-tpre));
            float tpost = fmaf(a_post, sdot[rowoff + 4 + n] * inv_rms, bias_post[n]);
            g_hpost[b * 4 + n] = 2.0f / (1.0f + expf(-tpost));
        }
        float M[4][4];
        #pragma unroll
        for (int m = 0; m < 4; m++)
            #pragma unroll
            for (int n = 0; n < 4; n++)
                M[m][n] = expf(fmaf(a_res, sdot[rowoff + 8 + m*4 + n] * inv_rms, bias_res[m*4 + n]));
        #pragma unroll 1
        for (int it = 0; it < 20; it++) {
            #pragma unroll
            for (int m = 0; m < 4; m++) {
                float rs = M[m][0] + M[m][1] + M[m][2] + M[m][3] + 1e-12f;
                float inv = 1.0f / rs;
                M[m][0] *= inv; M[m][1] *= inv; M[m][2] *= inv; M[m][3] *= inv;
            }
            #pragma unroll
            for (int n = 0; n < 4; n++) {
                float cs = M[0][n] + M[1][n] + M[2][n] + M[3][n] + 1e-12f;
                float inv = 1.0f / cs;
                M[0][n] *= inv; M[1][n] *= inv; M[2][n] *= inv; M[3][n] *= inv;
            }
        }
        #pragma unroll
        for (int m = 0; m < 4; m++)
            #pragma unroll
            for (int n = 0; n < 4; n++)
                sg[tid][4 + m*4 + n] = M[m][n];
    }
    __syncthreads();

    #pragma unroll
    for (int r = 0; r < 2; r++) {
        const int b = b0 + r;
        const float h0 = sg[r][0], h1 = sg[r][1], h2 = sg[r][2], h3 = sg[r][3];
        float R[4][4];
        #pragma unroll
        for (int m = 0; m < 4; m++)
            #pragma unroll
            for (int n = 0; n < 4; n++)
                R[m][n] = sg[r][4 + m*4 + n];

        const float4* sxr = sx4 + r * (FLT / 4);
        float4* fin4 = (float4*)(g_fin + (size_t)b * CD);
        #pragma unroll 1
        for (int c = tid; c < CD / 4; c += 256) {
            float4 x0 = sxr[c];
            float4 x1 = sxr[512 + c];
            float4 x2 = sxr[1024 + c];
            float4 x3 = sxr[1536 + c];
            float4 fv;
            fv.x = roundtf(h0*x0.x + h1*x1.x + h2*x2.x + h3*x3.x);
            fv.y = roundtf(h0*x0.y + h1*x1.y + h2*x2.y + h3*x3.y);
            fv.z = roundtf(h0*x0.z + h1*x1.z + h2*x2.z + h3*x3.z);
            fv.w = roundtf(h0*x0.w + h1*x1.w + h2*x2.w + h3*x3.w);
            fin4[c] = fv;
            #pragma unroll
            for (int m = 0; m < 4; m++) {
                float4 ov;
                ov.x = R[m][0]*x0.x + R[m][1]*x1.x + R[m][2]*x2.x + R[m][3]*x3.x;
                ov.y = R[m][0]*x0.y + R[m][1]*x1.y + R[m][2]*x2.y + R[m][3]*x3.y;
                ov.z = R[m][0]*x0.z + R[m][1]*x1.z + R[m][2]*x2.z + R[m][3]*x3.z;
                ov.w = R[m][0]*x0.w + R[m][1]*x1.w + R[m][2]*x2.w + R[m][3]*x3.w;
                ((float4*)(out + ((size_t)b * 4 + m) * CD))[c] = ov;
            }
        }
    }
}

// ---------------------------------------------------------------- tf32 GEMM
// Block tile 128x128, BK=32, 256 threads = 8 warps (2x4), warp tile 64x32.
// 2 CTAs/SM (107.5 KB smem, <=128 regs) for cross-CTA latency hiding.
#define STAGES 3
#define BKK 32
#define GBM 128
#define GBN 128
#define PA 36
#define PB 136
#define A_STG (GBM * PA)                  // 4608 floats
#define B_STG (BKK * PB)                  // 4352 floats
#define SMEM_GEMM ((STAGES * (A_STG + B_STG)) * 4)   // 107520 B

__device__ __forceinline__ void issue_chunk(
    const float* __restrict__ A, const float* __restrict__ Bm,
    int KDIM, int NDIM, int bm0, int bn0, int kt,
    uint32_t smA, uint32_t smB, int tid)
{
    #pragma unroll
    for (int q = 0; q < 4; q++) {
        int idx = q * 256 + tid;
        int row = idx >> 3;
        int c4 = idx & 7;
        cp16(smA + (row * PA + c4 * 4) * 4,
             A + (size_t)(bm0 + row) * KDIM + kt + c4 * 4);
    }
    #pragma unroll
    for (int q = 0; q < 4; q++) {
        int idx = q * 256 + tid;
        int row = idx >> 5;
        int c4 = idx & 31;
        cp16(smB + (row * PB + c4 * 4) * 4,
             Bm + (size_t)(kt + row) * NDIM + bn0 + c4 * 4);
    }
}

__device__ __forceinline__ void compute_chunk(
    const uint32_t* __restrict__ sA, const uint32_t* __restrict__ sB,
    int wm, int wn, int gid, int tig, float acc[4][4][4])
{
    #pragma unroll
    for (int kk = 0; kk < 4; kk++) {
        const int k0 = kk * 8;
        uint32_t af[4][4];
        #pragma unroll
        for (int mi = 0; mi < 4; mi++) {
            const uint32_t* ap = sA + (wm*64 + mi*16 + gid) * PA + k0 + tig;
            af[mi][0] = ap[0];
            af[mi][1] = ap[8 * PA];
            af[mi][2] = ap[4];
            af[mi][3] = ap[8 * PA + 4];
        }
        uint32_t bf[4][2];
        #pragma unroll
        for (int ni = 0; ni < 4; ni++) {
            const uint32_t* bp = sB + (k0 + tig) * PB + wn*32 + ni*8 + gid;
            bf[ni][0] = bp[0];
            bf[ni][1] = bp[4 * PB];
        }
        #pragma unroll
        for (int mi = 0; mi < 4; mi++)
            #pragma unroll
            for (int ni = 0; ni < 4; ni++)
                asm volatile(
                    "mma.sync.aligned.m16n8k8.row.col.f32.tf32.tf32.f32 "
                    "{%0,%1,%2,%3}, {%4,%5,%6,%7}, {%8,%9}, {%0,%1,%2,%3};\n"
                    : "+f"(acc[mi][ni][0]), "+f"(acc[mi][ni][1]),
                      "+f"(acc[mi][ni][2]), "+f"(acc[mi][ni][3])
                    : "r"(af[mi][0]), "r"(af[mi][1]), "r"(af[mi][2]), "r"(af[mi][3]),
                      "r"(bf[ni][0]), "r"(bf[ni][1]));
    }
}

__device__ __forceinline__ void gemm_mainloop(
    const float* __restrict__ A, const float* __restrict__ Bm,
    int KDIM, int NDIM, int bm0, int bn0,
    float* sm, float acc[4][4][4])
{
    const int tid = threadIdx.x;
    const int lane = tid & 31, wid = tid >> 5;
    const int wm = wid >> 2, wn = wid & 3;
    const int gid = lane >> 2, tig = lane & 3;

    float* sA = sm;
    float* sB = sm + STAGES * A_STG;
    const uint32_t sAu = smem_u32(sA);
    const uint32_t sBu = smem_u32(sB);

    const int nch = KDIM / BKK;

    #pragma unroll
    for (int i = 0; i < STAGES; i++) {
        issue_chunk(A, Bm, KDIM, NDIM, bm0, bn0, i * BKK,
                    sAu + i * A_STG * 4, sBu + i * B_STG * 4, tid);
        cp_commit();
    }

    for (int i = 0; i < nch; i++) {
        const int s = i % STAGES;
        cp_wait<STAGES - 1>();
        __syncthreads();
        compute_chunk((const uint32_t*)(sA + s * A_STG),
                      (const uint32_t*)(sB + s * B_STG), wm, wn, gid, tig, acc);
        __syncthreads();
        const int nx = i + STAGES;
        if (nx < nch)
            issue_chunk(A, Bm, KDIM, NDIM, bm0, bn0, nx * BKK,
                        sAu + s * A_STG * 4, sBu + s * B_STG * 4, tid);
        cp_commit();
    }
}

// GEMM1: g_hidden = round_tf32(gelu(g_fin @ W1r + b1));  M=4096, N=8192, K=2048
__global__ __launch_bounds__(256, 2) void gemm1_kernel(const float* __restrict__ b1)
{
    extern __shared__ float sm[];
    float acc[4][4][4];
    #pragma unroll
    for (int i = 0; i < 4; i++)
        #pragma unroll
        for (int j = 0; j < 4; j++)
            #pragma unroll
            for (int k = 0; k < 4; k++) acc[i][j][k] = 0.0f;

    const int bm0 = blockIdx.y * GBM;
    const int bn0 = blockIdx.x * GBN;
    gemm_mainloop(g_fin, g_w1r, CD, DFF, bm0, bn0, sm, acc);

    const int tid = threadIdx.x;
    const int lane = tid & 31, wid = tid >> 5;
    const int wm = wid >> 2, wn = wid & 3;
    const int gid = lane >> 2, tig = lane & 3;

    #pragma unroll
    for (int mi = 0; mi < 4; mi++) {
        int r0 = bm0 + wm*64 + mi*16 + gid;
        #pragma unroll
        for (int ni = 0; ni < 4; ni++) {
            int c = bn0 + wn*32 + ni*8 + tig*2;
            float2 bv = *(const float2*)(b1 + c);
            float2 v0, v1;
            v0.x = roundtf(gelu_tanh(acc[mi][ni][0] + bv.x));
            v0.y = roundtf(gelu_tanh(acc[mi][ni][1] + bv.y));
            v1.x = roundtf(gelu_tanh(acc[mi][ni][2] + bv.x));
            v1.y = roundtf(gelu_tanh(acc[mi][ni][3] + bv.y));
            *(float2*)(g_hidden + (size_t)r0 * DFF + c) = v0;
            *(float2*)(g_hidden + (size_t)(r0 + 8) * DFF + c) = v1;
        }
    }
}

__device__ __forceinline__ void epi2_row(float* __restrict__ out, int r, int c,
                                         float f0, float f1, float4 hp) {
    float hv[4] = {hp.x, hp.y, hp.z, hp.w};
    #pragma unroll
    for (int m = 0; m < 4; m++) {
        float2* p = (float2*)(out + ((size_t)r * 4 + m) * CD + c);
        float2 o = *p;
        o.x = fmaf(hv[m], f0, o.x);
        o.y = fmaf(hv[m], f1, o.y);
        *p = o;
    }
}

// GEMM2: out[b,m,:] += hpost[b,m]*(g_hidden @ W2r + b2);  M=4096, N=2048, K=8192
__global__ __launch_bounds__(256, 2) void gemm2_kernel(
    const float* __restrict__ b2, float* __restrict__ out)
{
    extern __shared__ float sm[];
    float acc[4][4][4];
    #pragma unroll
    for (int i = 0; i < 4; i++)
        #pragma unroll
        for (int j = 0; j < 4; j++)
            #pragma unroll
            for (int k = 0; k < 4; k++) acc[i][j][k] = 0.0f;

    const int bm0 = blockIdx.y * GBM;
    const int bn0 = blockIdx.x * GBN;
    gemm_mainloop(g_hidden, g_w2r, DFF, CD, bm0, bn0, sm, acc);

    const int tid = threadIdx.x;
    const int lane = tid & 31, wid = tid >> 5;
    const int wm = wid >> 2, wn = wid & 3;
    const int gid = lane >> 2, tig = lane & 3;

    #pragma unroll
    for (int mi = 0; mi < 4; mi++) {
        int r0 = bm0 + wm*64 + mi*16 + gid;
        int r1 = r0 + 8;
        float4 hp0 = *(const float4*)(g_hpost + r0 * 4);
        float4 hp1 = *(const float4*)(g_hpost + r1 * 4);
        #pragma unroll
        for (int ni = 0; ni < 4; ni++) {
            int c = bn0 + wn*32 + ni*8 + tig*2;
            float2 bv = *(const float2*)(b2 + c);
            epi2_row(out, r0, c, acc[mi][ni][0] + bv.x, acc[mi][ni][1] + bv.y, hp0);
            epi2_row(out, r1, c, acc[mi][ni][2] + bv.x, acc[mi][ni][3] + bv.y, hp1);
        }
    }
}

// ---------------------------------------------------------------- launch
extern "C" void kernel_launch(void* const* d_in, const int* in_sizes, int n_in,
                              void* d_out, int out_size) {
    (void)in_sizes; (void)n_in; (void)out_size;
    const float* x         = (const float*)d_in[0];
    const float* phi_pre   = (const float*)d_in[1];
    const float* phi_post  = (const float*)d_in[2];
    const float* phi_res   = (const float*)d_in[3];
    const float* bias_pre  = (const float*)d_in[4];
    const float* bias_post = (const float*)d_in[5];
    const float* bias_res  = (const float*)d_in[6];
    const float* alpha_pre = (const float*)d_in[7];
    const float* alpha_post= (const float*)d_in[8];
    const float* alpha_res = (const float*)d_in[9];
    const float* W1        = (const float*)d_in[10];
    const float* b1        = (const float*)d_in[11];
    const float* W2        = (const float*)d_in[12];
    const float* b2        = (const float*)d_in[13];
    float* out = (float*)d_out;

    static float* w1r_ptr = nullptr;
    static float* w2r_ptr = nullptr;
    if (!w1r_ptr) {
        cudaGetSymbolAddress((void**)&w1r_ptr, g_w1r);
        cudaGetSymbolAddress((void**)&w2r_ptr, g_w2r);
        cudaFuncSetAttribute(gemm1_kernel, cudaFuncAttributeMaxDynamicSharedMemorySize, SMEM_GEMM);
        cudaFuncSetAttribute(gemm2_kernel, cudaFuncAttributeMaxDynamicSharedMemorySize, SMEM_GEMM);
        cudaFuncSetAttribute(gates_kernel, cudaFuncAttributeMaxDynamicSharedMemorySize, 2 * FLT * 4);
    }

    const int n4 = (CD * DFF) / 4;
    round_kernel<<<(n4 + 255) / 256, 256>>>(W1, w1r_ptr, n4);
    round_kernel<<<(n4 + 255) / 256, 256>>>(W2, w2r_ptr, n4);

    gates_kernel<<<BR / 2, 256, 2 * FLT * 4>>>(x, phi_pre, phi_post, phi_res,
                                               bias_pre, bias_post, bias_res,
                                               alpha_pre, alpha_post, alpha_res, out);

    gemm1_kernel<<<dim3(DFF / GBN, BR / GBM), 256, SMEM_GEMM>>>(b1);
    gemm2_kernel<<<dim3(CD / GBN, BR / GBM), 256, SMEM_GEMM>>>(b2, out);
}

// round 6
// speedup vs baseline: 1.2351x; 1.0122x over previous
#include <cuda_runtime.h>
#include <cstdint>

#define NS 4
#define CD 2048
#define FLT 8192
#define BR 4096
#define DFF 8192

// ---------------------------------------------------------------- scratch
__device__ float g_fin[(size_t)BR * CD];        // (B, C)    32 MB  (tf32-rounded)
__device__ float g_hidden[(size_t)BR * DFF];    // (B, DFF) 128 MB  (tf32-rounded)
__device__ float g_hpost[BR * NS];              // (B, 4)
__device__ float g_w1r[(size_t)CD * DFF];       // W1 rounded  64 MB
__device__ float g_w2r[(size_t)DFF * CD];       // W2 rounded  64 MB

// ---------------------------------------------------------------- helpers
__device__ __forceinline__ float fast_tanhf(float u) {
    float e = __expf(2.0f * u);
    return 1.0f - __fdividef(2.0f, e + 1.0f);
}
__device__ __forceinline__ float gelu_tanh(float x) {
    float u = 0.7978845608028654f * fmaf(0.044715f * x, x * x, x);
    return 0.5f * x * (1.0f + fast_tanhf(u));
}
__device__ __forceinline__ uint32_t f2tf32(float x) {
    uint32_t u;
    asm("cvt.rna.tf32.f32 %0, %1;" : "=r"(u) : "f"(x));
    return u;
}
__device__ __forceinline__ float roundtf(float x) { return __uint_as_float(f2tf32(x)); }
__device__ __forceinline__ uint32_t smem_u32(const void* p) {
    uint32_t a;
    asm("{ .reg .u64 t; cvta.to.shared.u64 t, %1; cvt.u32.u64 %0, t; }" : "=r"(a) : "l"(p));
    return a;
}
__device__ __forceinline__ void cp16(uint32_t dst, const void* src) {
    asm volatile("cp.async.cg.shared.global [%0], [%1], 16;" :: "r"(dst), "l"(src));
}
__device__ __forceinline__ void cp_commit() {
    asm volatile("cp.async.commit_group;" ::: "memory");
}
template <int N>
__device__ __forceinline__ void cp_wait() {
    asm volatile("cp.async.wait_group %0;" :: "n"(N) : "memory");
}

// ---------------------------------------------------------------- weight prep (tf32 round)
__global__ __launch_bounds__(256) void round_kernel(
    const float* __restrict__ src, float* __restrict__ dst, int n4)
{
    int i = blockIdx.x * 256 + threadIdx.x;
    if (i < n4) {
        float4 v = ((const float4*)src)[i];
        v.x = roundtf(v.x); v.y = roundtf(v.y);
        v.z = roundtf(v.z); v.w = roundtf(v.w);
        ((float4*)dst)[i] = v;
    }
}

// ---------------------------------------------------------------- gates (2 rows/block)
__global__ __launch_bounds__(256) void gates_kernel(
    const float* __restrict__ x,
    const float* __restrict__ phi_pre,
    const float* __restrict__ phi_post,
    const float* __restrict__ phi_res,
    const float* __restrict__ bias_pre,
    const float* __restrict__ bias_post,
    const float* __restrict__ bias_res,
    const float* __restrict__ alpha_pre_p,
    const float* __restrict__ alpha_post_p,
    const float* __restrict__ alpha_res_p,
    float* __restrict__ out)
{
    extern __shared__ float sx[];           // 2 * FLT floats (64 KB)
    __shared__ float sred[8][50];
    __shared__ float sdot[50];
    __shared__ float sg[2][20];

    const int tid = threadIdx.x;
    const int b0 = blockIdx.x * 2;

    const float4* xr = (const float4*)(x + (size_t)b0 * FLT);
    float4* sx4 = (float4*)sx;
    #pragma unroll 4
    for (int i = tid; i < 2 * FLT / 4; i += 256) sx4[i] = xr[i];
    __syncthreads();

    float acc[50];
    #pragma unroll
    for (int j = 0; j < 50; j++) acc[j] = 0.0f;

    const float4* pp4 = (const float4*)phi_pre;
    const float4* pq4 = (const float4*)phi_post;
    const float4* pr4 = (const float4*)phi_res;

    for (int f = tid; f < FLT; f += 256) {
        float xv0 = sx[f];
        float xv1 = sx[FLT + f];
        acc[24] = fmaf(xv0, xv0, acc[24]);
        acc[49] = fmaf(xv1, xv1, acc[49]);
        float4 p = pp4[f];
        acc[0] = fmaf(xv0, p.x, acc[0]);   acc[25] = fmaf(xv1, p.x, acc[25]);
        acc[1] = fmaf(xv0, p.y, acc[1]);   acc[26] = fmaf(xv1, p.y, acc[26]);
        acc[2] = fmaf(xv0, p.z, acc[2]);   acc[27] = fmaf(xv1, p.z, acc[27]);
        acc[3] = fmaf(xv0, p.w, acc[3]);   acc[28] = fmaf(xv1, p.w, acc[28]);
        float4 q = pq4[f];
        acc[4] = fmaf(xv0, q.x, acc[4]);   acc[29] = fmaf(xv1, q.x, acc[29]);
        acc[5] = fmaf(xv0, q.y, acc[5]);   acc[30] = fmaf(xv1, q.y, acc[30]);
        acc[6] = fmaf(xv0, q.z, acc[6]);   acc[31] = fmaf(xv1, q.z, acc[31]);
        acc[7] = fmaf(xv0, q.w, acc[7]);   acc[32] = fmaf(xv1, q.w, acc[32]);
        #pragma unroll
        for (int r = 0; r < 4; r++) {
            float4 rr = pr4[f * 4 + r];
            acc[8 + r*4 + 0] = fmaf(xv0, rr.x, acc[8 + r*4 + 0]);
            acc[8 + r*4 + 1] = fmaf(xv0, rr.y, acc[8 + r*4 + 1]);
            acc[8 + r*4 + 2] = fmaf(xv0, rr.z, acc[8 + r*4 + 2]);
            acc[8 + r*4 + 3] = fmaf(xv0, rr.w, acc[8 + r*4 + 3]);
            acc[33 + r*4 + 0] = fmaf(xv1, rr.x, acc[33 + r*4 + 0]);
            acc[33 + r*4 + 1] = fmaf(xv1, rr.y, acc[33 + r*4 + 1]);
            acc[33 + r*4 + 2] = fmaf(xv1, rr.z, acc[33 + r*4 + 2]);
            acc[33 + r*4 + 3] = fmaf(xv1, rr.w, acc[33 + r*4 + 3]);
        }
    }

    const int lane = tid & 31, warp = tid >> 5;
    #pragma unroll
    for (int j = 0; j < 50; j++) {
        float v = acc[j];
        v += __shfl_xor_sync(0xffffffffu, v, 16);
        v += __shfl_xor_sync(0xffffffffu, v, 8);
        v += __shfl_xor_sync(0xffffffffu, v, 4);
        v += __shfl_xor_sync(0xffffffffu, v, 2);
        v += __shfl_xor_sync(0xffffffffu, v, 1);
        if (lane == 0) sred[warp][j] = v;
    }
    __syncthreads();
    if (tid < 50) {
        float s = 0.0f;
        #pragma unroll
        for (int w = 0; w < 8; w++) s += sred[w][tid];
        sdot[tid] = s;
    }
    __syncthreads();
    if (tid < 2) {
        const int rowoff = tid * 25;
        const int b = b0 + tid;
        float inv_rms = rsqrtf(sdot[rowoff + 24] * (1.0f / (float)FLT) + 1e-8f);
        float a_pre = alpha_pre_p[0], a_post = alpha_post_p[0], a_res = alpha_res_p[0];
        #pragma unroll
        for (int n = 0; n < 4; n++) {
            float tpre = fmaf(a_pre, sdot[rowoff + n] * inv_rms, bias_pre[n]);
            sg[tid][n] = 1.0f / (1.0f + expf(-tpre));
            float tpost = fmaf(a_post, sdot[rowoff + 4 + n] * inv_rms, bias_post[n]);
            g_hpost[b * 4 + n] = 2.0f / (1.0f + expf(-tpost));
        }
        float M[4][4];
        #pragma unroll
        for (int m = 0; m < 4; m++)
            #pragma unroll
            for (int n = 0; n < 4; n++)
                M[m][n] = expf(fmaf(a_res, sdot[rowoff + 8 + m*4 + n] * inv_rms, bias_res[m*4 + n]));
        #pragma unroll 1
        for (int it = 0; it < 20; it++) {
            #pragma unroll
            for (int m = 0; m < 4; m++) {
                float rs = M[m][0] + M[m][1] + M[m][2] + M[m][3] + 1e-12f;
                float inv = 1.0f / rs;
                M[m][0] *= inv; M[m][1] *= inv; M[m][2] *= inv; M[m][3] *= inv;
            }
            #pragma unroll
            for (int n = 0; n < 4; n++) {
                float cs = M[0][n] + M[1][n] + M[2][n] + M[3][n] + 1e-12f;
                float inv = 1.0f / cs;
                M[0][n] *= inv; M[1][n] *= inv; M[2][n] *= inv; M[3][n] *= inv;
            }
        }
        #pragma unroll
        for (int m = 0; m < 4; m++)
            #pragma unroll
            for (int n = 0; n < 4; n++)
                sg[tid][4 + m*4 + n] = M[m][n];
    }
    __syncthreads();

    #pragma unroll
    for (int r = 0; r < 2; r++) {
        const int b = b0 + r;
        const float h0 = sg[r][0], h1 = sg[r][1], h2 = sg[r][2], h3 = sg[r][3];
        float R[4][4];
        #pragma unroll
        for (int m = 0; m < 4; m++)
            #pragma unroll
            for (int n = 0; n < 4; n++)
                R[m][n] = sg[r][4 + m*4 + n];

        const float4* sxr = sx4 + r * (FLT / 4);
        float4* fin4 = (float4*)(g_fin + (size_t)b * CD);
        #pragma unroll 1
        for (int c = tid; c < CD / 4; c += 256) {
            float4 x0 = sxr[c];
            float4 x1 = sxr[512 + c];
            float4 x2 = sxr[1024 + c];
            float4 x3 = sxr[1536 + c];
            float4 fv;
            fv.x = roundtf(h0*x0.x + h1*x1.x + h2*x2.x + h3*x3.x);
            fv.y = roundtf(h0*x0.y + h1*x1.y + h2*x2.y + h3*x3.y);
            fv.z = roundtf(h0*x0.z + h1*x1.z + h2*x2.z + h3*x3.z);
            fv.w = roundtf(h0*x0.w + h1*x1.w + h2*x2.w + h3*x3.w);
            fin4[c] = fv;
            #pragma unroll
            for (int m = 0; m < 4; m++) {
                float4 ov;
                ov.x = R[m][0]*x0.x + R[m][1]*x1.x + R[m][2]*x2.x + R[m][3]*x3.x;
                ov.y = R[m][0]*x0.y + R[m][1]*x1.y + R[m][2]*x2.y + R[m][3]*x3.y;
                ov.z = R[m][0]*x0.z + R[m][1]*x1.z + R[m][2]*x2.z + R[m][3]*x3.z;
                ov.w = R[m][0]*x0.w + R[m][1]*x1.w + R[m][2]*x2.w + R[m][3]*x3.w;
                ((float4*)(out + ((size_t)b * 4 + m) * CD))[c] = ov;
            }
        }
    }
}

// ---------------------------------------------------------------- tf32 GEMM
// Block tile 128x128, BK=32, 128 threads = 4 warps (2x2), warp tile 64x64.
// LDS:MMA = 1:1 per warp; 2 CTAs/SM; STAGES=3 cp.async pipeline.
#define STAGES 3
#define BKK 32
#define GBM 128
#define GBN 128
#define GT 128                            // threads per CTA
#define PA 36
#define PB 136
#define A_STG (GBM * PA)                  // 4608 floats
#define B_STG (BKK * PB)                  // 4352 floats
#define SMEM_GEMM ((STAGES * (A_STG + B_STG)) * 4)   // 107520 B

__device__ __forceinline__ void issue_chunk(
    const float* __restrict__ A, const float* __restrict__ Bm,
    int KDIM, int NDIM, int bm0, int bn0, int kt,
    uint32_t smA, uint32_t smB, int tid)
{
    #pragma unroll
    for (int q = 0; q < 8; q++) {
        int idx = q * GT + tid;
        int row = idx >> 3;
        int c4 = idx & 7;
        cp16(smA + (row * PA + c4 * 4) * 4,
             A + (size_t)(bm0 + row) * KDIM + kt + c4 * 4);
    }
    #pragma unroll
    for (int q = 0; q < 8; q++) {
        int idx = q * GT + tid;
        int row = idx >> 5;
        int c4 = idx & 31;
        cp16(smB + (row * PB + c4 * 4) * 4,
             Bm + (size_t)(kt + row) * NDIM + bn0 + c4 * 4);
    }
}

__device__ __forceinline__ void compute_chunk(
    const uint32_t* __restrict__ sA, const uint32_t* __restrict__ sB,
    int wm, int wn, int gid, int tig, float acc[4][8][4])
{
    #pragma unroll
    for (int kk = 0; kk < 4; kk++) {
        const int k0 = kk * 8;
        uint32_t af[4][4];
        #pragma unroll
        for (int mi = 0; mi < 4; mi++) {
            const uint32_t* ap = sA + (wm*64 + mi*16 + gid) * PA + k0 + tig;
            af[mi][0] = ap[0];
            af[mi][1] = ap[8 * PA];
            af[mi][2] = ap[4];
            af[mi][3] = ap[8 * PA + 4];
        }
        uint32_t bf[8][2];
        #pragma unroll
        for (int ni = 0; ni < 8; ni++) {
            const uint32_t* bp = sB + (k0 + tig) * PB + wn*64 + ni*8 + gid;
            bf[ni][0] = bp[0];
            bf[ni][1] = bp[4 * PB];
        }
        #pragma unroll
        for (int mi = 0; mi < 4; mi++)
            #pragma unroll
            for (int ni = 0; ni < 8; ni++)
                asm volatile(
                    "mma.sync.aligned.m16n8k8.row.col.f32.tf32.tf32.f32 "
                    "{%0,%1,%2,%3}, {%4,%5,%6,%7}, {%8,%9}, {%0,%1,%2,%3};\n"
                    : "+f"(acc[mi][ni][0]), "+f"(acc[mi][ni][1]),
                      "+f"(acc[mi][ni][2]), "+f"(acc[mi][ni][3])
                    : "r"(af[mi][0]), "r"(af[mi][1]), "r"(af[mi][2]), "r"(af[mi][3]),
                      "r"(bf[ni][0]), "r"(bf[ni][1]));
    }
}

__device__ __forceinline__ void gemm_mainloop(
    const float* __restrict__ A, const float* __restrict__ Bm,
    int KDIM, int NDIM, int bm0, int bn0,
    float* sm, float acc[4][8][4])
{
    const int tid = threadIdx.x;
    const int lane = tid & 31, wid = tid >> 5;
    const int wm = wid >> 1, wn = wid & 1;
    const int gid = lane >> 2, tig = lane & 3;

    float* sA = sm;
    float* sB = sm + STAGES * A_STG;
    const uint32_t sAu = smem_u32(sA);
    const uint32_t sBu = smem_u32(sB);

    const int nch = KDIM / BKK;

    #pragma unroll
    for (int i = 0; i < STAGES; i++) {
        issue_chunk(A, Bm, KDIM, NDIM, bm0, bn0, i * BKK,
                    sAu + i * A_STG * 4, sBu + i * B_STG * 4, tid);
        cp_commit();
    }

    for (int i = 0; i < nch; i++) {
        const int s = i % STAGES;
        cp_wait<STAGES - 1>();
        __syncthreads();
        compute_chunk((const uint32_t*)(sA + s * A_STG),
                      (const uint32_t*)(sB + s * B_STG), wm, wn, gid, tig, acc);
        __syncthreads();
        const int nx = i + STAGES;
        if (nx < nch)
            issue_chunk(A, Bm, KDIM, NDIM, bm0, bn0, nx * BKK,
                        sAu + s * A_STG * 4, sBu + s * B_STG * 4, tid);
        cp_commit();
    }
}

// GEMM1: g_hidden = round_tf32(gelu(g_fin @ W1r + b1));  M=4096, N=8192, K=2048
__global__ __launch_bounds__(GT, 2) void gemm1_kernel(const float* __restrict__ b1)
{
    extern __shared__ float sm[];
    float acc[4][8][4];
    #pragma unroll
    for (int i = 0; i < 4; i++)
        #pragma unroll
        for (int j = 0; j < 8; j++)
            #pragma unroll
            for (int k = 0; k < 4; k++) acc[i][j][k] = 0.0f;

    const int bm0 = blockIdx.y * GBM;
    const int bn0 = blockIdx.x * GBN;
    gemm_mainloop(g_fin, g_w1r, CD, DFF, bm0, bn0, sm, acc);

    const int tid = threadIdx.x;
    const int lane = tid & 31, wid = tid >> 5;
    const int wm = wid >> 1, wn = wid & 1;
    const int gid = lane >> 2, tig = lane & 3;

    #pragma unroll
    for (int mi = 0; mi < 4; mi++) {
        int r0 = bm0 + wm*64 + mi*16 + gid;
        #pragma unroll
        for (int ni = 0; ni < 8; ni++) {
            int c = bn0 + wn*64 + ni*8 + tig*2;
            float2 bv = *(const float2*)(b1 + c);
            float2 v0, v1;
            v0.x = roundtf(gelu_tanh(acc[mi][ni][0] + bv.x));
            v0.y = roundtf(gelu_tanh(acc[mi][ni][1] + bv.y));
            v1.x = roundtf(gelu_tanh(acc[mi][ni][2] + bv.x));
            v1.y = roundtf(gelu_tanh(acc[mi][ni][3] + bv.y));
            *(float2*)(g_hidden + (size_t)r0 * DFF + c) = v0;
            *(float2*)(g_hidden + (size_t)(r0 + 8) * DFF + c) = v1;
        }
    }
}

__device__ __forceinline__ void epi2_row(float* __restrict__ out, int r, int c,
                                         float f0, float f1, float4 hp) {
    float hv[4] = {hp.x, hp.y, hp.z, hp.w};
    #pragma unroll
    for (int m = 0; m < 4; m++) {
        float2* p = (float2*)(out + ((size_t)r * 4 + m) * CD + c);
        float2 o = *p;
        o.x = fmaf(hv[m], f0, o.x);
        o.y = fmaf(hv[m], f1, o.y);
        *p = o;
    }
}

// GEMM2: out[b,m,:] += hpost[b,m]*(g_hidden @ W2r + b2);  M=4096, N=2048, K=8192
__global__ __launch_bounds__(GT, 2) void gemm2_kernel(
    const float* __restrict__ b2, float* __restrict__ out)
{
    extern __shared__ float sm[];
    float acc[4][8][4];
    #pragma unroll
    for (int i = 0; i < 4; i++)
        #pragma unroll
        for (int j = 0; j < 8; j++)
            #pragma unroll
            for (int k = 0; k < 4; k++) acc[i][j][k] = 0.0f;

    const int bm0 = blockIdx.y * GBM;
    const int bn0 = blockIdx.x * GBN;
    gemm_mainloop(g_hidden, g_w2r, DFF, CD, bm0, bn0, sm, acc);

    const int tid = threadIdx.x;
    const int lane = tid & 31, wid = tid >> 5;
    const int wm = wid >> 1, wn = wid & 1;
    const int gid = lane >> 2, tig = lane & 3;

    #pragma unroll
    for (int mi = 0; mi < 4; mi++) {
        int r0 = bm0 + wm*64 + mi*16 + gid;
        int r1 = r0 + 8;
        float4 hp0 = *(const float4*)(g_hpost + r0 * 4);
        float4 hp1 = *(const float4*)(g_hpost + r1 * 4);
        #pragma unroll
        for (int ni = 0; ni < 8; ni++) {
            int c = bn0 + wn*64 + ni*8 + tig*2;
            float2 bv = *(const float2*)(b2 + c);
            epi2_row(out, r0, c, acc[mi][ni][0] + bv.x, acc[mi][ni][1] + bv.y, hp0);
            epi2_row(out, r1, c, acc[mi][ni][2] + bv.x, acc[mi][ni][3] + bv.y, hp1);
        }
    }
}

// ---------------------------------------------------------------- launch
extern "C" void kernel_launch(void* const* d_in, const int* in_sizes, int n_in,
                              void* d_out, int out_size) {
    (void)in_sizes; (void)n_in; (void)out_size;
    const float* x         = (const float*)d_in[0];
    const float* phi_pre   = (const float*)d_in[1];
    const float* phi_post  = (const float*)d_in[2];
    const float* phi_res   = (const float*)d_in[3];
    const float* bias_pre  = (const float*)d_in[4];
    const float* bias_post = (const float*)d_in[5];
    const float* bias_res  = (const float*)d_in[6];
    const float* alpha_pre = (const float*)d_in[7];
    const float* alpha_post= (const float*)d_in[8];
    const float* alpha_res = (const float*)d_in[9];
    const float* W1        = (const float*)d_in[10];
    const float* b1        = (const float*)d_in[11];
    const float* W2        = (const float*)d_in[12];
    const float* b2        = (const float*)d_in[13];
    float* out = (float*)d_out;

    static float* w1r_ptr = nullptr;
    static float* w2r_ptr = nullptr;
    if (!w1r_ptr) {
        cudaGetSymbolAddress((void**)&w1r_ptr, g_w1r);
        cudaGetSymbolAddress((void**)&w2r_ptr, g_w2r);
        cudaFuncSetAttribute(gemm1_kernel, cudaFuncAttributeMaxDynamicSharedMemorySize, SMEM_GEMM);
        cudaFuncSetAttribute(gemm2_kernel, cudaFuncAttributeMaxDynamicSharedMemorySize, SMEM_GEMM);
        cudaFuncSetAttribute(gates_kernel, cudaFuncAttributeMaxDynamicSharedMemorySize, 2 * FLT * 4);
    }

    const int n4 = (CD * DFF) / 4;
    round_kernel<<<(n4 + 255) / 256, 256>>>(W1, w1r_ptr, n4);
    round_kernel<<<(n4 + 255) / 256, 256>>>(W2, w2r_ptr, n4);

    gates_kernel<<<BR / 2, 256, 2 * FLT * 4>>>(x, phi_pre, phi_post, phi_res,
                                               bias_pre, bias_post, bias_res,
                                               alpha_pre, alpha_post, alpha_res, out);

    gemm1_kernel<<<dim3(DFF / GBN, BR / GBM), GT, SMEM_GEMM>>>(b1);
    gemm2_kernel<<<dim3(CD / GBN, BR / GBM), GT, SMEM_GEMM>>>(b2, out);
}

// round 7
// speedup vs baseline: 1.4380x; 1.1643x over previous
#include <cuda_runtime.h>
#include <cstdint>

#define NS 4
#define CD 2048
#define FLT 8192
#define BR 4096
#define DFF 8192

// ---------------------------------------------------------------- scratch
__device__ float g_fin[(size_t)BR * CD];        // (B, C)    32 MB  (tf32-rounded)
__device__ float g_hidden[(size_t)BR * DFF];    // (B, DFF) 128 MB  (tf32-rounded)
__device__ float g_hpost[BR * NS];              // (B, 4)
__device__ float g_w1r[(size_t)CD * DFF];       // W1 rounded  64 MB
__device__ float g_w2r[(size_t)DFF * CD];       // W2 rounded  64 MB

// ---------------------------------------------------------------- helpers
__device__ __forceinline__ float fast_tanhf(float u) {
    float e = __expf(2.0f * u);
    return 1.0f - __fdividef(2.0f, e + 1.0f);
}
__device__ __forceinline__ float gelu_tanh(float x) {
    float u = 0.7978845608028654f * fmaf(0.044715f * x, x * x, x);
    return 0.5f * x * (1.0f + fast_tanhf(u));
}
__device__ __forceinline__ uint32_t f2tf32(float x) {
    uint32_t u;
    asm("cvt.rna.tf32.f32 %0, %1;" : "=r"(u) : "f"(x));
    return u;
}
__device__ __forceinline__ float roundtf(float x) { return __uint_as_float(f2tf32(x)); }
__device__ __forceinline__ uint32_t smem_u32(const void* p) {
    uint32_t a;
    asm("{ .reg .u64 t; cvta.to.shared.u64 t, %1; cvt.u32.u64 %0, t; }" : "=r"(a) : "l"(p));
    return a;
}
__device__ __forceinline__ void cp16(uint32_t dst, const void* src) {
    asm volatile("cp.async.cg.shared.global [%0], [%1], 16;" :: "r"(dst), "l"(src));
}
__device__ __forceinline__ void cp_commit() {
    asm volatile("cp.async.commit_group;" ::: "memory");
}
template <int N>
__device__ __forceinline__ void cp_wait() {
    asm volatile("cp.async.wait_group %0;" :: "n"(N) : "memory");
}

// ---------------------------------------------------------------- weight prep (tf32 round)
__global__ __launch_bounds__(256) void round_kernel(
    const float* __restrict__ src, float* __restrict__ dst, int n4)
{
    int i = blockIdx.x * 256 + threadIdx.x;
    if (i < n4) {
        float4 v = ((const float4*)src)[i];
        v.x = roundtf(v.x); v.y = roundtf(v.y);
        v.z = roundtf(v.z); v.w = roundtf(v.w);
        ((float4*)dst)[i] = v;
    }
}

// ---------------------------------------------------------------- gates (2 rows/block)
__global__ __launch_bounds__(256) void gates_kernel(
    const float* __restrict__ x,
    const float* __restrict__ phi_pre,
    const float* __restrict__ phi_post,
    const float* __restrict__ phi_res,
    const float* __restrict__ bias_pre,
    const float* __restrict__ bias_post,
    const float* __restrict__ bias_res,
    const float* __restrict__ alpha_pre_p,
    const float* __restrict__ alpha_post_p,
    const float* __restrict__ alpha_res_p,
    float* __restrict__ out)
{
    extern __shared__ float sx[];           // 2 * FLT floats (64 KB)
    __shared__ float sred[8][50];
    __shared__ float sdot[50];
    __shared__ float sg[2][20];

    const int tid = threadIdx.x;
    const int b0 = blockIdx.x * 2;

    const float4* xr = (const float4*)(x + (size_t)b0 * FLT);
    float4* sx4 = (float4*)sx;
    #pragma unroll 4
    for (int i = tid; i < 2 * FLT / 4; i += 256) sx4[i] = xr[i];
    __syncthreads();

    float acc[50];
    #pragma unroll
    for (int j = 0; j < 50; j++) acc[j] = 0.0f;

    const float4* pp4 = (const float4*)phi_pre;
    const float4* pq4 = (const float4*)phi_post;
    const float4* pr4 = (const float4*)phi_res;

    for (int f = tid; f < FLT; f += 256) {
        float xv0 = sx[f];
        float xv1 = sx[FLT + f];
        acc[24] = fmaf(xv0, xv0, acc[24]);
        acc[49] = fmaf(xv1, xv1, acc[49]);
        float4 p = pp4[f];
        acc[0] = fmaf(xv0, p.x, acc[0]);   acc[25] = fmaf(xv1, p.x, acc[25]);
        acc[1] = fmaf(xv0, p.y, acc[1]);   acc[26] = fmaf(xv1, p.y, acc[26]);
        acc[2] = fmaf(xv0, p.z, acc[2]);   acc[27] = fmaf(xv1, p.z, acc[27]);
        acc[3] = fmaf(xv0, p.w, acc[3]);   acc[28] = fmaf(xv1, p.w, acc[28]);
        float4 q = pq4[f];
        acc[4] = fmaf(xv0, q.x, acc[4]);   acc[29] = fmaf(xv1, q.x, acc[29]);
        acc[5] = fmaf(xv0, q.y, acc[5]);   acc[30] = fmaf(xv1, q.y, acc[30]);
        acc[6] = fmaf(xv0, q.z, acc[6]);   acc[31] = fmaf(xv1, q.z, acc[31]);
        acc[7] = fmaf(xv0, q.w, acc[7]);   acc[32] = fmaf(xv1, q.w, acc[32]);
        #pragma unroll
        for (int r = 0; r < 4; r++) {
            float4 rr = pr4[f * 4 + r];
            acc[8 + r*4 + 0] = fmaf(xv0, rr.x, acc[8 + r*4 + 0]);
            acc[8 + r*4 + 1] = fmaf(xv0, rr.y, acc[8 + r*4 + 1]);
            acc[8 + r*4 + 2] = fmaf(xv0, rr.z, acc[8 + r*4 + 2]);
            acc[8 + r*4 + 3] = fmaf(xv0, rr.w, acc[8 + r*4 + 3]);
            acc[33 + r*4 + 0] = fmaf(xv1, rr.x, acc[33 + r*4 + 0]);
            acc[33 + r*4 + 1] = fmaf(xv1, rr.y, acc[33 + r*4 + 1]);
            acc[33 + r*4 + 2] = fmaf(xv1, rr.z, acc[33 + r*4 + 2]);
            acc[33 + r*4 + 3] = fmaf(xv1, rr.w, acc[33 + r*4 + 3]);
        }
    }

    const int lane = tid & 31, warp = tid >> 5;
    #pragma unroll
    for (int j = 0; j < 50; j++) {
        float v = acc[j];
        v += __shfl_xor_sync(0xffffffffu, v, 16);
        v += __shfl_xor_sync(0xffffffffu, v, 8);
        v += __shfl_xor_sync(0xffffffffu, v, 4);
        v += __shfl_xor_sync(0xffffffffu, v, 2);
        v += __shfl_xor_sync(0xffffffffu, v, 1);
        if (lane == 0) sred[warp][j] = v;
    }
    __syncthreads();
    if (tid < 50) {
        float s = 0.0f;
        #pragma unroll
        for (int w = 0; w < 8; w++) s += sred[w][tid];
        sdot[tid] = s;
    }
    __syncthreads();
    if (tid < 2) {
        const int rowoff = tid * 25;
        const int b = b0 + tid;
        float inv_rms = rsqrtf(sdot[rowoff + 24] * (1.0f / (float)FLT) + 1e-8f);
        float a_pre = alpha_pre_p[0], a_post = alpha_post_p[0], a_res = alpha_res_p[0];
        #pragma unroll
        for (int n = 0; n < 4; n++) {
            float tpre = fmaf(a_pre, sdot[rowoff + n] * inv_rms, bias_pre[n]);
            sg[tid][n] = 1.0f / (1.0f + expf(-tpre));
            float tpost = fmaf(a_post, sdot[rowoff + 4 + n] * inv_rms, bias_post[n]);
            g_hpost[b * 4 + n] = 2.0f / (1.0f + expf(-tpost));
        }
        float M[4][4];
        #pragma unroll
        for (int m = 0; m < 4; m++)
            #pragma unroll
            for (int n = 0; n < 4; n++)
                M[m][n] = expf(fmaf(a_res, sdot[rowoff + 8 + m*4 + n] * inv_rms, bias_res[m*4 + n]));
        #pragma unroll 1
        for (int it = 0; it < 20; it++) {
            #pragma unroll
            for (int m = 0; m < 4; m++) {
                float rs = M[m][0] + M[m][1] + M[m][2] + M[m][3] + 1e-12f;
                float inv = 1.0f / rs;
                M[m][0] *= inv; M[m][1] *= inv; M[m][2] *= inv; M[m][3] *= inv;
            }
            #pragma unroll
            for (int n = 0; n < 4; n++) {
                float cs = M[0][n] + M[1][n] + M[2][n] + M[3][n] + 1e-12f;
                float inv = 1.0f / cs;
                M[0][n] *= inv; M[1][n] *= inv; M[2][n] *= inv; M[3][n] *= inv;
            }
        }
        #pragma unroll
        for (int m = 0; m < 4; m++)
            #pragma unroll
            for (int n = 0; n < 4; n++)
                sg[tid][4 + m*4 + n] = M[m][n];
    }
    __syncthreads();

    #pragma unroll
    for (int r = 0; r < 2; r++) {
        const int b = b0 + r;
        const float h0 = sg[r][0], h1 = sg[r][1], h2 = sg[r][2], h3 = sg[r][3];
        float R[4][4];
        #pragma unroll
        for (int m = 0; m < 4; m++)
            #pragma unroll
            for (int n = 0; n < 4; n++)
                R[m][n] = sg[r][4 + m*4 + n];

        const float4* sxr = sx4 + r * (FLT / 4);
        float4* fin4 = (float4*)(g_fin + (size_t)b * CD);
        #pragma unroll 1
        for (int c = tid; c < CD / 4; c += 256) {
            float4 x0 = sxr[c];
            float4 x1 = sxr[512 + c];
            float4 x2 = sxr[1024 + c];
            float4 x3 = sxr[1536 + c];
            float4 fv;
            fv.x = roundtf(h0*x0.x + h1*x1.x + h2*x2.x + h3*x3.x);
            fv.y = roundtf(h0*x0.y + h1*x1.y + h2*x2.y + h3*x3.y);
            fv.z = roundtf(h0*x0.z + h1*x1.z + h2*x2.z + h3*x3.z);
            fv.w = roundtf(h0*x0.w + h1*x1.w + h2*x2.w + h3*x3.w);
            fin4[c] = fv;
            #pragma unroll
            for (int m = 0; m < 4; m++) {
                float4 ov;
                ov.x = R[m][0]*x0.x + R[m][1]*x1.x + R[m][2]*x2.x + R[m][3]*x3.x;
                ov.y = R[m][0]*x0.y + R[m][1]*x1.y + R[m][2]*x2.y + R[m][3]*x3.y;
                ov.z = R[m][0]*x0.z + R[m][1]*x1.z + R[m][2]*x2.z + R[m][3]*x3.z;
                ov.w = R[m][0]*x0.w + R[m][1]*x1.w + R[m][2]*x2.w + R[m][3]*x3.w;
                ((float4*)(out + ((size_t)b * 4 + m) * CD))[c] = ov;
            }
        }
    }
}

// ---------------------------------------------------------------- tf32 GEMM
// Block tile 128x128, BK=32, 128 threads = 4 warps (2x2), warp tile 64x64.
// Single-sync multistage: one __syncthreads per chunk, cp.async for chunk
// i+STAGES-1 interleaved between MMA groups of chunk i.
#define STAGES 3
#define BKK 32
#define GBM 128
#define GBN 128
#define GT 128                            // threads per CTA
#define PA 36
#define PB 136
#define A_STG (GBM * PA)                  // 4608 floats
#define B_STG (BKK * PB)                  // 4352 floats
#define SMEM_GEMM ((STAGES * (A_STG + B_STG)) * 4)   // 107520 B

__device__ __forceinline__ void issue_chunk(
    const float* __restrict__ A, const float* __restrict__ Bm,
    int KDIM, int NDIM, int bm0, int bn0, int kt,
    uint32_t smA, uint32_t smB, int tid)
{
    #pragma unroll
    for (int q = 0; q < 8; q++) {
        int idx = q * GT + tid;
        int row = idx >> 3;
        int c4 = idx & 7;
        cp16(smA + (row * PA + c4 * 4) * 4,
             A + (size_t)(bm0 + row) * KDIM + kt + c4 * 4);
    }
    #pragma unroll
    for (int q = 0; q < 8; q++) {
        int idx = q * GT + tid;
        int row = idx >> 5;
        int c4 = idx & 31;
        cp16(smB + (row * PB + c4 * 4) * 4,
             Bm + (size_t)(kt + row) * NDIM + bn0 + c4 * 4);
    }
}

__device__ __forceinline__ void gemm_mainloop(
    const float* __restrict__ A, const float* __restrict__ Bm,
    int KDIM, int NDIM, int bm0, int bn0,
    float* sm, float acc[4][8][4])
{
    const int tid = threadIdx.x;
    const int lane = tid & 31, wid = tid >> 5;
    const int wm = wid >> 1, wn = wid & 1;
    const int gid = lane >> 2, tig = lane & 3;

    float* sA = sm;
    float* sB = sm + STAGES * A_STG;
    const uint32_t sAu = smem_u32(sA);
    const uint32_t sBu = smem_u32(sB);

    const int nch = KDIM / BKK;

    #pragma unroll
    for (int i = 0; i < STAGES - 1; i++) {
        issue_chunk(A, Bm, KDIM, NDIM, bm0, bn0, i * BKK,
                    sAu + i * A_STG * 4, sBu + i * B_STG * 4, tid);
        cp_commit();
    }

    for (int i = 0; i < nch; i++) {
        cp_wait<STAGES - 2>();
        __syncthreads();
        const uint32_t* sAc = (const uint32_t*)(sA + (i % STAGES) * A_STG);
        const uint32_t* sBc = (const uint32_t*)(sB + (i % STAGES) * B_STG);
        const int nx = i + STAGES - 1;
        const bool doio = nx < nch;
        const uint32_t wAu = sAu + (nx % STAGES) * A_STG * 4;
        const uint32_t wBu = sBu + (nx % STAGES) * B_STG * 4;
        const int kt = nx * BKK;

        #pragma unroll
        for (int kk = 0; kk < 4; kk++) {
            const int k0 = kk * 8;
            uint32_t af[4][4];
            #pragma unroll
            for (int mi = 0; mi < 4; mi++) {
                const uint32_t* ap = sAc + (wm*64 + mi*16 + gid) * PA + k0 + tig;
                af[mi][0] = ap[0];
                af[mi][1] = ap[8 * PA];
                af[mi][2] = ap[4];
                af[mi][3] = ap[8 * PA + 4];
            }
            uint32_t bf[8][2];
            #pragma unroll
            for (int ni = 0; ni < 8; ni++) {
                const uint32_t* bp = sBc + (k0 + tig) * PB + wn*64 + ni*8 + gid;
                bf[ni][0] = bp[0];
                bf[ni][1] = bp[4 * PB];
            }
            // interleave next-chunk loads (4 cp.async per kk step)
            if (doio) {
                #pragma unroll
                for (int q = kk * 2; q < kk * 2 + 2; q++) {
                    int idx = q * GT + tid;
                    int row = idx >> 3;
                    int c4 = idx & 7;
                    cp16(wAu + (row * PA + c4 * 4) * 4,
                         A + (size_t)(bm0 + row) * KDIM + kt + c4 * 4);
                }
                #pragma unroll
                for (int q = kk * 2; q < kk * 2 + 2; q++) {
                    int idx = q * GT + tid;
                    int row = idx >> 5;
                    int c4 = idx & 31;
                    cp16(wBu + (row * PB + c4 * 4) * 4,
                         Bm + (size_t)(kt + row) * NDIM + bn0 + c4 * 4);
                }
            }
            #pragma unroll
            for (int mi = 0; mi < 4; mi++)
                #pragma unroll
                for (int ni = 0; ni < 8; ni++)
                    asm volatile(
                        "mma.sync.aligned.m16n8k8.row.col.f32.tf32.tf32.f32 "
                        "{%0,%1,%2,%3}, {%4,%5,%6,%7}, {%8,%9}, {%0,%1,%2,%3};\n"
                        : "+f"(acc[mi][ni][0]), "+f"(acc[mi][ni][1]),
                          "+f"(acc[mi][ni][2]), "+f"(acc[mi][ni][3])
                        : "r"(af[mi][0]), "r"(af[mi][1]), "r"(af[mi][2]), "r"(af[mi][3]),
                          "r"(bf[ni][0]), "r"(bf[ni][1]));
        }
        cp_commit();
    }
}

// GEMM1: g_hidden = round_tf32(gelu(g_fin @ W1r + b1));  M=4096, N=8192, K=2048
__global__ __launch_bounds__(GT, 2) void gemm1_kernel(const float* __restrict__ b1)
{
    extern __shared__ float sm[];
    float acc[4][8][4];
    #pragma unroll
    for (int i = 0; i < 4; i++)
        #pragma unroll
        for (int j = 0; j < 8; j++)
            #pragma unroll
            for (int k = 0; k < 4; k++) acc[i][j][k] = 0.0f;

    const int bm0 = blockIdx.y * GBM;
    const int bn0 = blockIdx.x * GBN;
    gemm_mainloop(g_fin, g_w1r, CD, DFF, bm0, bn0, sm, acc);

    const int tid = threadIdx.x;
    const int lane = tid & 31, wid = tid >> 5;
    const int wm = wid >> 1, wn = wid & 1;
    const int gid = lane >> 2, tig = lane & 3;

    #pragma unroll
    for (int mi = 0; mi < 4; mi++) {
        int r0 = bm0 + wm*64 + mi*16 + gid;
        #pragma unroll
        for (int ni = 0; ni < 8; ni++) {
            int c = bn0 + wn*64 + ni*8 + tig*2;
            float2 bv = *(const float2*)(b1 + c);
            float2 v0, v1;
            v0.x = roundtf(gelu_tanh(acc[mi][ni][0] + bv.x));
            v0.y = roundtf(gelu_tanh(acc[mi][ni][1] + bv.y));
            v1.x = roundtf(gelu_tanh(acc[mi][ni][2] + bv.x));
            v1.y = roundtf(gelu_tanh(acc[mi][ni][3] + bv.y));
            *(float2*)(g_hidden + (size_t)r0 * DFF + c) = v0;
            *(float2*)(g_hidden + (size_t)(r0 + 8) * DFF + c) = v1;
        }
    }
}

__device__ __forceinline__ void epi2_row(float* __restrict__ out, int r, int c,
                                         float f0, float f1, float4 hp) {
    float hv[4] = {hp.x, hp.y, hp.z, hp.w};
    #pragma unroll
    for (int m = 0; m < 4; m++) {
        float2* p = (float2*)(out + ((size_t)r * 4 + m) * CD + c);
        float2 o = *p;
        o.x = fmaf(hv[m], f0, o.x);
        o.y = fmaf(hv[m], f1, o.y);
        *p = o;
    }
}

// GEMM2: out[b,m,:] += hpost[b,m]*(g_hidden @ W2r + b2);  M=4096, N=2048, K=8192
__global__ __launch_bounds__(GT, 2) void gemm2_kernel(
    const float* __restrict__ b2, float* __restrict__ out)
{
    extern __shared__ float sm[];
    float acc[4][8][4];
    #pragma unroll
    for (int i = 0; i < 4; i++)
        #pragma unroll
        for (int j = 0; j < 8; j++)
            #pragma unroll
            for (int k = 0; k < 4; k++) acc[i][j][k] = 0.0f;

    const int bm0 = blockIdx.y * GBM;
    const int bn0 = blockIdx.x * GBN;
    gemm_mainloop(g_hidden, g_w2r, DFF, CD, bm0, bn0, sm, acc);

    const int tid = threadIdx.x;
    const int lane = tid & 31, wid = tid >> 5;
    const int wm = wid >> 1, wn = wid & 1;
    const int gid = lane >> 2, tig = lane & 3;

    #pragma unroll
    for (int mi = 0; mi < 4; mi++) {
        int r0 = bm0 + wm*64 + mi*16 + gid;
        int r1 = r0 + 8;
        float4 hp0 = *(const float4*)(g_hpost + r0 * 4);
        float4 hp1 = *(const float4*)(g_hpost + r1 * 4);
        #pragma unroll
        for (int ni = 0; ni < 8; ni++) {
            int c = bn0 + wn*64 + ni*8 + tig*2;
            float2 bv = *(const float2*)(b2 + c);
            epi2_row(out, r0, c, acc[mi][ni][0] + bv.x, acc[mi][ni][1] + bv.y, hp0);
            epi2_row(out, r1, c, acc[mi][ni][2] + bv.x, acc[mi][ni][3] + bv.y, hp1);
        }
    }
}

// ---------------------------------------------------------------- launch
extern "C" void kernel_launch(void* const* d_in, const int* in_sizes, int n_in,
                              void* d_out, int out_size) {
    (void)in_sizes; (void)n_in; (void)out_size;
    const float* x         = (const float*)d_in[0];
    const float* phi_pre   = (const float*)d_in[1];
    const float* phi_post  = (const float*)d_in[2];
    const float* phi_res   = (const float*)d_in[3];
    const float* bias_pre  = (const float*)d_in[4];
    const float* bias_post = (const float*)d_in[5];
    const float* bias_res  = (const float*)d_in[6];
    const float* alpha_pre = (const float*)d_in[7];
    const float* alpha_post= (const float*)d_in[8];
    const float* alpha_res = (const float*)d_in[9];
    const float* W1        = (const float*)d_in[10];
    const float* b1        = (const float*)d_in[11];
    const float* W2        = (const float*)d_in[12];
    const float* b2        = (const float*)d_in[13];
    float* out = (float*)d_out;

    static float* w1r_ptr = nullptr;
    static float* w2r_ptr = nullptr;
    if (!w1r_ptr) {
        cudaGetSymbolAddress((void**)&w1r_ptr, g_w1r);
        cudaGetSymbolAddress((void**)&w2r_ptr, g_w2r);
        cudaFuncSetAttribute(gemm1_kernel, cudaFuncAttributeMaxDynamicSharedMemorySize, SMEM_GEMM);
        cudaFuncSetAttribute(gemm2_kernel, cudaFuncAttributeMaxDynamicSharedMemorySize, SMEM_GEMM);
        cudaFuncSetAttribute(gates_kernel, cudaFuncAttributeMaxDynamicSharedMemorySize, 2 * FLT * 4);
    }

    const int n4 = (CD * DFF) / 4;
    round_kernel<<<(n4 + 255) / 256, 256>>>(W1, w1r_ptr, n4);
    round_kernel<<<(n4 + 255) / 256, 256>>>(W2, w2r_ptr, n4);

    gates_kernel<<<BR / 2, 256, 2 * FLT * 4>>>(x, phi_pre, phi_post, phi_res,
                                               bias_pre, bias_post, bias_res,
                                               alpha_pre, alpha_post, alpha_res, out);

    gemm1_kernel<<<dim3(DFF / GBN, BR / GBM), GT, SMEM_GEMM>>>(b1);
    gemm2_kernel<<<dim3(CD / GBN, BR / GBM), GT, SMEM_GEMM>>>(b2, out);
}

// round 8
// speedup vs baseline: 1.4475x; 1.0066x over previous
#include <cuda_runtime.h>
#include <cstdint>

#define NS 4
#define CD 2048
#define FLT 8192
#define BR 4096
#define DFF 8192

// ---------------------------------------------------------------- scratch
__device__ float g_fin[(size_t)BR * CD];        // (B, C)    32 MB  (tf32-rounded)
__device__ float g_hidden[(size_t)BR * DFF];    // (B, DFF) 128 MB  (tf32-rounded)
__device__ float g_hpost[BR * NS];              // (B, 4)
__device__ float g_w1r[(size_t)CD * DFF];       // W1 rounded  64 MB
__device__ float g_w2r[(size_t)DFF * CD];       // W2 rounded  64 MB

// ---------------------------------------------------------------- helpers
__device__ __forceinline__ float fast_tanhf(float u) {
    float e = __expf(2.0f * u);
    return 1.0f - __fdividef(2.0f, e + 1.0f);
}
__device__ __forceinline__ float gelu_tanh(float x) {
    float u = 0.7978845608028654f * fmaf(0.044715f * x, x * x, x);
    return 0.5f * x * (1.0f + fast_tanhf(u));
}
__device__ __forceinline__ uint32_t f2tf32(float x) {
    uint32_t u;
    asm("cvt.rna.tf32.f32 %0, %1;" : "=r"(u) : "f"(x));
    return u;
}
__device__ __forceinline__ float roundtf(float x) { return __uint_as_float(f2tf32(x)); }
__device__ __forceinline__ uint32_t smem_u32(const void* p) {
    uint32_t a;
    asm("{ .reg .u64 t; cvta.to.shared.u64 t, %1; cvt.u32.u64 %0, t; }" : "=r"(a) : "l"(p));
    return a;
}
__device__ __forceinline__ void cp16(uint32_t dst, const void* src) {
    asm volatile("cp.async.cg.shared.global [%0], [%1], 16;" :: "r"(dst), "l"(src));
}
__device__ __forceinline__ void cp_commit() {
    asm volatile("cp.async.commit_group;" ::: "memory");
}
template <int N>
__device__ __forceinline__ void cp_wait() {
    asm volatile("cp.async.wait_group %0;" :: "n"(N) : "memory");
}

// ---------------------------------------------------------------- weight prep (tf32 round)
__global__ __launch_bounds__(256) void round_kernel(
    const float* __restrict__ src, float* __restrict__ dst, int n4)
{
    int i = blockIdx.x * 256 + threadIdx.x;
    if (i < n4) {
        float4 v = ((const float4*)src)[i];
        v.x = roundtf(v.x); v.y = roundtf(v.y);
        v.z = roundtf(v.z); v.w = roundtf(v.w);
        ((float4*)dst)[i] = v;
    }
}

// ---------------------------------------------------------------- gates (4 rows/block)
#define GROWS 4
__global__ __launch_bounds__(256) void gates_kernel(
    const float* __restrict__ x,
    const float* __restrict__ phi_pre,
    const float* __restrict__ phi_post,
    const float* __restrict__ phi_res,
    const float* __restrict__ bias_pre,
    const float* __restrict__ bias_post,
    const float* __restrict__ bias_res,
    const float* __restrict__ alpha_pre_p,
    const float* __restrict__ alpha_post_p,
    const float* __restrict__ alpha_res_p,
    float* __restrict__ out)
{
    extern __shared__ float sx[];           // GROWS * FLT floats (128 KB)
    __shared__ float sred[8][GROWS * 25];
    __shared__ float sdot[GROWS * 25];
    __shared__ float sg[GROWS][20];

    const int tid = threadIdx.x;
    const int b0 = blockIdx.x * GROWS;

    const float4* xr = (const float4*)(x + (size_t)b0 * FLT);
    float4* sx4 = (float4*)sx;
    #pragma unroll 4
    for (int i = tid; i < GROWS * FLT / 4; i += 256) sx4[i] = xr[i];
    __syncthreads();

    float acc[GROWS * 25];
    #pragma unroll
    for (int j = 0; j < GROWS * 25; j++) acc[j] = 0.0f;

    const float4* pp4 = (const float4*)phi_pre;
    const float4* pq4 = (const float4*)phi_post;
    const float4* pr4 = (const float4*)phi_res;

    for (int f = tid; f < FLT; f += 256) {
        float xv[GROWS];
        #pragma unroll
        for (int r = 0; r < GROWS; r++) {
            xv[r] = sx[r * FLT + f];
            acc[r * 25 + 24] = fmaf(xv[r], xv[r], acc[r * 25 + 24]);
        }
        float4 p = pp4[f];
        #pragma unroll
        for (int r = 0; r < GROWS; r++) {
            acc[r*25 + 0] = fmaf(xv[r], p.x, acc[r*25 + 0]);
            acc[r*25 + 1] = fmaf(xv[r], p.y, acc[r*25 + 1]);
            acc[r*25 + 2] = fmaf(xv[r], p.z, acc[r*25 + 2]);
            acc[r*25 + 3] = fmaf(xv[r], p.w, acc[r*25 + 3]);
        }
        float4 q = pq4[f];
        #pragma unroll
        for (int r = 0; r < GROWS; r++) {
            acc[r*25 + 4] = fmaf(xv[r], q.x, acc[r*25 + 4]);
            acc[r*25 + 5] = fmaf(xv[r], q.y, acc[r*25 + 5]);
            acc[r*25 + 6] = fmaf(xv[r], q.z, acc[r*25 + 6]);
            acc[r*25 + 7] = fmaf(xv[r], q.w, acc[r*25 + 7]);
        }
        #pragma unroll
        for (int g = 0; g < 4; g++) {
            float4 rr = pr4[f * 4 + g];
            #pragma unroll
            for (int r = 0; r < GROWS; r++) {
                acc[r*25 + 8 + g*4 + 0] = fmaf(xv[r], rr.x, acc[r*25 + 8 + g*4 + 0]);
                acc[r*25 + 8 + g*4 + 1] = fmaf(xv[r], rr.y, acc[r*25 + 8 + g*4 + 1]);
                acc[r*25 + 8 + g*4 + 2] = fmaf(xv[r], rr.z, acc[r*25 + 8 + g*4 + 2]);
                acc[r*25 + 8 + g*4 + 3] = fmaf(xv[r], rr.w, acc[r*25 + 8 + g*4 + 3]);
            }
        }
    }

    const int lane = tid & 31, warp = tid >> 5;
    #pragma unroll
    for (int j = 0; j < GROWS * 25; j++) {
        float v = acc[j];
        v += __shfl_xor_sync(0xffffffffu, v, 16);
        v += __shfl_xor_sync(0xffffffffu, v, 8);
        v += __shfl_xor_sync(0xffffffffu, v, 4);
        v += __shfl_xor_sync(0xffffffffu, v, 2);
        v += __shfl_xor_sync(0xffffffffu, v, 1);
        if (lane == 0) sred[warp][j] = v;
    }
    __syncthreads();
    if (tid < GROWS * 25) {
        float s = 0.0f;
        #pragma unroll
        for (int w = 0; w < 8; w++) s += sred[w][tid];
        sdot[tid] = s;
    }
    __syncthreads();
    if (tid < GROWS) {
        const int rowoff = tid * 25;
        const int b = b0 + tid;
        float inv_rms = rsqrtf(sdot[rowoff + 24] * (1.0f / (float)FLT) + 1e-8f);
        float a_pre = alpha_pre_p[0], a_post = alpha_post_p[0], a_res = alpha_res_p[0];
        #pragma unroll
        for (int n = 0; n < 4; n++) {
            float tpre = fmaf(a_pre, sdot[rowoff + n] * inv_rms, bias_pre[n]);
            sg[tid][n] = 1.0f / (1.0f + expf(-tpre));
            float tpost = fmaf(a_post, sdot[rowoff + 4 + n] * inv_rms, bias_post[n]);
            g_hpost[b * 4 + n] = 2.0f / (1.0f + expf(-tpost));
        }
        float M[4][4];
        #pragma unroll
        for (int m = 0; m < 4; m++)
            #pragma unroll
            for (int n = 0; n < 4; n++)
                M[m][n] = expf(fmaf(a_res, sdot[rowoff + 8 + m*4 + n] * inv_rms, bias_res[m*4 + n]));
        #pragma unroll 1
        for (int it = 0; it < 20; it++) {
            #pragma unroll
            for (int m = 0; m < 4; m++) {
                float rs = M[m][0] + M[m][1] + M[m][2] + M[m][3] + 1e-12f;
                float inv = 1.0f / rs;
                M[m][0] *= inv; M[m][1] *= inv; M[m][2] *= inv; M[m][3] *= inv;
            }
            #pragma unroll
            for (int n = 0; n < 4; n++) {
                float cs = M[0][n] + M[1][n] + M[2][n] + M[3][n] + 1e-12f;
                float inv = 1.0f / cs;
                M[0][n] *= inv; M[1][n] *= inv; M[2][n] *= inv; M[3][n] *= inv;
            }
        }
        #pragma unroll
        for (int m = 0; m < 4; m++)
            #pragma unroll
            for (int n = 0; n < 4; n++)
                sg[tid][4 + m*4 + n] = M[m][n];
    }
    __syncthreads();

    #pragma unroll 1
    for (int r = 0; r < GROWS; r++) {
        const int b = b0 + r;
        const float h0 = sg[r][0], h1 = sg[r][1], h2 = sg[r][2], h3 = sg[r][3];
        float R[4][4];
        #pragma unroll
        for (int m = 0; m < 4; m++)
            #pragma unroll
            for (int n = 0; n < 4; n++)
                R[m][n] = sg[r][4 + m*4 + n];

        const float4* sxr = sx4 + r * (FLT / 4);
        float4* fin4 = (float4*)(g_fin + (size_t)b * CD);
        #pragma unroll 1
        for (int c = tid; c < CD / 4; c += 256) {
            float4 x0 = sxr[c];
            float4 x1 = sxr[512 + c];
            float4 x2 = sxr[1024 + c];
            float4 x3 = sxr[1536 + c];
            float4 fv;
            fv.x = roundtf(h0*x0.x + h1*x1.x + h2*x2.x + h3*x3.x);
            fv.y = roundtf(h0*x0.y + h1*x1.y + h2*x2.y + h3*x3.y);
            fv.z = roundtf(h0*x0.z + h1*x1.z + h2*x2.z + h3*x3.z);
            fv.w = roundtf(h0*x0.w + h1*x1.w + h2*x2.w + h3*x3.w);
            fin4[c] = fv;
            #pragma unroll
            for (int m = 0; m < 4; m++) {
                float4 ov;
                ov.x = R[m][0]*x0.x + R[m][1]*x1.x + R[m][2]*x2.x + R[m][3]*x3.x;
                ov.y = R[m][0]*x0.y + R[m][1]*x1.y + R[m][2]*x2.y + R[m][3]*x3.y;
                ov.z = R[m][0]*x0.z + R[m][1]*x1.z + R[m][2]*x2.z + R[m][3]*x3.z;
                ov.w = R[m][0]*x0.w + R[m][1]*x1.w + R[m][2]*x2.w + R[m][3]*x3.w;
                ((float4*)(out + ((size_t)b * 4 + m) * CD))[c] = ov;
            }
        }
    }
}

// ---------------------------------------------------------------- tf32 GEMM
// Block tile 128x128, BK=32, 128 threads = 4 warps (2x2), warp tile 64x64.
// Single-sync multistage; rolling stage indices (no % in loop).
#define STAGES 3
#define BKK 32
#define GBM 128
#define GBN 128
#define GT 128                            // threads per CTA
#define PA 36
#define PB 136
#define A_STG (GBM * PA)                  // 4608 floats
#define B_STG (BKK * PB)                  // 4352 floats
#define SMEM_GEMM ((STAGES * (A_STG + B_STG)) * 4)   // 107520 B

__device__ __forceinline__ void issue_chunk(
    const float* __restrict__ A, const float* __restrict__ Bm,
    int KDIM, int NDIM, int bm0, int bn0, int kt,
    uint32_t smA, uint32_t smB, int tid)
{
    #pragma unroll
    for (int q = 0; q < 8; q++) {
        int idx = q * GT + tid;
        int row = idx >> 3;
        int c4 = idx & 7;
        cp16(smA + (row * PA + c4 * 4) * 4,
             A + (size_t)(bm0 + row) * KDIM + kt + c4 * 4);
    }
    #pragma unroll
    for (int q = 0; q < 8; q++) {
        int idx = q * GT + tid;
        int row = idx >> 5;
        int c4 = idx & 31;
        cp16(smB + (row * PB + c4 * 4) * 4,
             Bm + (size_t)(kt + row) * NDIM + bn0 + c4 * 4);
    }
}

__device__ __forceinline__ void gemm_mainloop(
    const float* __restrict__ A, const float* __restrict__ Bm,
    int KDIM, int NDIM, int bm0, int bn0,
    float* sm, float acc[4][8][4])
{
    const int tid = threadIdx.x;
    const int lane = tid & 31, wid = tid >> 5;
    const int wm = wid >> 1, wn = wid & 1;
    const int gid = lane >> 2, tig = lane & 3;

    float* sA = sm;
    float* sB = sm + STAGES * A_STG;
    const uint32_t sAu = smem_u32(sA);
    const uint32_t sBu = smem_u32(sB);

    const int nch = KDIM / BKK;

    #pragma unroll
    for (int i = 0; i < STAGES - 1; i++) {
        issue_chunk(A, Bm, KDIM, NDIM, bm0, bn0, i * BKK,
                    sAu + i * A_STG * 4, sBu + i * B_STG * 4, tid);
        cp_commit();
    }

    // rolling indices
    int sc = 0;                 // consume stage
    int sw = STAGES - 1;        // write stage ((i+STAGES-1) % STAGES)
    const float* Akt = A + (STAGES - 1) * BKK;    // A + kt for write chunk
    const float* Bkt = Bm + (size_t)(STAGES - 1) * BKK * NDIM;

    for (int i = 0; i < nch; i++) {
        cp_wait<STAGES - 2>();
        __syncthreads();
        const uint32_t* sAc = (const uint32_t*)(sA + sc * A_STG);
        const uint32_t* sBc = (const uint32_t*)(sB + sc * B_STG);
        const bool doio = (i + STAGES - 1) < nch;
        const uint32_t wAu = sAu + sw * A_STG * 4;
        const uint32_t wBu = sBu + sw * B_STG * 4;

        #pragma unroll
        for (int kk = 0; kk < 4; kk++) {
            const int k0 = kk * 8;
            uint32_t af[4][4];
            #pragma unroll
            for (int mi = 0; mi < 4; mi++) {
                const uint32_t* ap = sAc + (wm*64 + mi*16 + gid) * PA + k0 + tig;
                af[mi][0] = ap[0];
                af[mi][1] = ap[8 * PA];
                af[mi][2] = ap[4];
                af[mi][3] = ap[8 * PA + 4];
            }
            uint32_t bf[8][2];
            #pragma unroll
            for (int ni = 0; ni < 8; ni++) {
                const uint32_t* bp = sBc + (k0 + tig) * PB + wn*64 + ni*8 + gid;
                bf[ni][0] = bp[0];
                bf[ni][1] = bp[4 * PB];
            }
            // interleave next-chunk loads (4 cp.async per kk step)
            if (doio) {
                #pragma unroll
                for (int q = kk * 2; q < kk * 2 + 2; q++) {
                    int idx = q * GT + tid;
                    int row = idx >> 3;
                    int c4 = idx & 7;
                    cp16(wAu + (row * PA + c4 * 4) * 4,
                         Akt + (size_t)(bm0 + row) * KDIM + c4 * 4);
                }
                #pragma unroll
                for (int q = kk * 2; q < kk * 2 + 2; q++) {
                    int idx = q * GT + tid;
                    int row = idx >> 5;
                    int c4 = idx & 31;
                    cp16(wBu + (row * PB + c4 * 4) * 4,
                         Bkt + (size_t)row * NDIM + bn0 + c4 * 4);
                }
            }
            #pragma unroll
            for (int mi = 0; mi < 4; mi++)
                #pragma unroll
                for (int ni = 0; ni < 8; ni++)
                    asm volatile(
                        "mma.sync.aligned.m16n8k8.row.col.f32.tf32.tf32.f32 "
                        "{%0,%1,%2,%3}, {%4,%5,%6,%7}, {%8,%9}, {%0,%1,%2,%3};\n"
                        : "+f"(acc[mi][ni][0]), "+f"(acc[mi][ni][1]),
                          "+f"(acc[mi][ni][2]), "+f"(acc[mi][ni][3])
                        : "r"(af[mi][0]), "r"(af[mi][1]), "r"(af[mi][2]), "r"(af[mi][3]),
                          "r"(bf[ni][0]), "r"(bf[ni][1]));
        }
        cp_commit();
        sc = (sc + 1 == STAGES) ? 0 : sc + 1;
        sw = (sw + 1 == STAGES) ? 0 : sw + 1;
        Akt += BKK;
        Bkt += (size_t)BKK * NDIM;
    }
}

// GEMM1: g_hidden = round_tf32(gelu(g_fin @ W1r + b1));  M=4096, N=8192, K=2048
__global__ __launch_bounds__(GT, 2) void gemm1_kernel(const float* __restrict__ b1)
{
    extern __shared__ float sm[];
    float acc[4][8][4];
    #pragma unroll
    for (int i = 0; i < 4; i++)
        #pragma unroll
        for (int j = 0; j < 8; j++)
            #pragma unroll
            for (int k = 0; k < 4; k++) acc[i][j][k] = 0.0f;

    const int bm0 = blockIdx.y * GBM;
    const int bn0 = blockIdx.x * GBN;
    gemm_mainloop(g_fin, g_w1r, CD, DFF, bm0, bn0, sm, acc);

    const int tid = threadIdx.x;
    const int lane = tid & 31, wid = tid >> 5;
    const int wm = wid >> 1, wn = wid & 1;
    const int gid = lane >> 2, tig = lane & 3;

    #pragma unroll
    for (int mi = 0; mi < 4; mi++) {
        int r0 = bm0 + wm*64 + mi*16 + gid;
        #pragma unroll
        for (int ni = 0; ni < 8; ni++) {
            int c = bn0 + wn*64 + ni*8 + tig*2;
            float2 bv = *(const float2*)(b1 + c);
            float2 v0, v1;
            v0.x = roundtf(gelu_tanh(acc[mi][ni][0] + bv.x));
            v0.y = roundtf(gelu_tanh(acc[mi][ni][1] + bv.y));
            v1.x = roundtf(gelu_tanh(acc[mi][ni][2] + bv.x));
            v1.y = roundtf(gelu_tanh(acc[mi][ni][3] + bv.y));
            *(float2*)(g_hidden + (size_t)r0 * DFF + c) = v0;
            *(float2*)(g_hidden + (size_t)(r0 + 8) * DFF + c) = v1;
        }
    }
}

__device__ __forceinline__ void epi2_row(float* __restrict__ out, int r, int c,
                                         float f0, float f1, float4 hp) {
    float hv[4] = {hp.x, hp.y, hp.z, hp.w};
    #pragma unroll
    for (int m = 0; m < 4; m++) {
        float2* p = (float2*)(out + ((size_t)r * 4 + m) * CD + c);
        float2 o = *p;
        o.x = fmaf(hv[m], f0, o.x);
        o.y = fmaf(hv[m], f1, o.y);
        *p = o;
    }
}

// GEMM2: out[b,m,:] += hpost[b,m]*(g_hidden @ W2r + b2);  M=4096, N=2048, K=8192
__global__ __launch_bounds__(GT, 2) void gemm2_kernel(
    const float* __restrict__ b2, float* __restrict__ out)
{
    extern __shared__ float sm[];
    float acc[4][8][4];
    #pragma unroll
    for (int i = 0; i < 4; i++)
        #pragma unroll
        for (int j = 0; j < 8; j++)
            #pragma unroll
            for (int k = 0; k < 4; k++) acc[i][j][k] = 0.0f;

    const int bm0 = blockIdx.y * GBM;
    const int bn0 = blockIdx.x * GBN;
    gemm_mainloop(g_hidden, g_w2r, DFF, CD, bm0, bn0, sm, acc);

    const int tid = threadIdx.x;
    const int lane = tid & 31, wid = tid >> 5;
    const int wm = wid >> 1, wn = wid & 1;
    const int gid = lane >> 2, tig = lane & 3;

    #pragma unroll
    for (int mi = 0; mi < 4; mi++) {
        int r0 = bm0 + wm*64 + mi*16 + gid;
        int r1 = r0 + 8;
        float4 hp0 = *(const float4*)(g_hpost + r0 * 4);
        float4 hp1 = *(const float4*)(g_hpost + r1 * 4);
        #pragma unroll
        for (int ni = 0; ni < 8; ni++) {
            int c = bn0 + wn*64 + ni*8 + tig*2;
            float2 bv = *(const float2*)(b2 + c);
            epi2_row(out, r0, c, acc[mi][ni][0] + bv.x, acc[mi][ni][1] + bv.y, hp0);
            epi2_row(out, r1, c, acc[mi][ni][2] + bv.x, acc[mi][ni][3] + bv.y, hp1);
        }
    }
}

// ---------------------------------------------------------------- launch
extern "C" void kernel_launch(void* const* d_in, const int* in_sizes, int n_in,
                              void* d_out, int out_size) {
    (void)in_sizes; (void)n_in; (void)out_size;
    const float* x         = (const float*)d_in[0];
    const float* phi_pre   = (const float*)d_in[1];
    const float* phi_post  = (const float*)d_in[2];
    const float* phi_res   = (const float*)d_in[3];
    const float* bias_pre  = (const float*)d_in[4];
    const float* bias_post = (const float*)d_in[5];
    const float* bias_res  = (const float*)d_in[6];
    const float* alpha_pre = (const float*)d_in[7];
    const float* alpha_post= (const float*)d_in[8];
    const float* alpha_res = (const float*)d_in[9];
    const float* W1        = (const float*)d_in[10];
    const float* b1        = (const float*)d_in[11];
    const float* W2        = (const float*)d_in[12];
    const float* b2        = (const float*)d_in[13];
    float* out = (float*)d_out;

    static float* w1r_ptr = nullptr;
    static float* w2r_ptr = nullptr;
    if (!w1r_ptr) {
        cudaGetSymbolAddress((void**)&w1r_ptr, g_w1r);
        cudaGetSymbolAddress((void**)&w2r_ptr, g_w2r);
        cudaFuncSetAttribute(gemm1_kernel, cudaFuncAttributeMaxDynamicSharedMemorySize, SMEM_GEMM);
        cudaFuncSetAttribute(gemm2_kernel, cudaFuncAttributeMaxDynamicSharedMemorySize, SMEM_GEMM);
        cudaFuncSetAttribute(gates_kernel, cudaFuncAttributeMaxDynamicSharedMemorySize, GROWS * FLT * 4);
    }

    const int n4 = (CD * DFF) / 4;
    round_kernel<<<(n4 + 255) / 256, 256>>>(W1, w1r_ptr, n4);
    round_kernel<<<(n4 + 255) / 256, 256>>>(W2, w2r_ptr, n4);

    gates_kernel<<<BR / GROWS, 256, GROWS * FLT * 4>>>(x, phi_pre, phi_post, phi_res,
                                                       bias_pre, bias_post, bias_res,
                                                       alpha_pre, alpha_post, alpha_res, out);

    gemm1_kernel<<<dim3(DFF / GBN, BR / GBM), GT, SMEM_GEMM>>>(b1);
    gemm2_kernel<<<dim3(CD / GBN, BR / GBM), GT, SMEM_GEMM>>>(b2, out);
}